// round 1
// baseline (speedup 1.0000x reference)
#include <cuda_runtime.h>
#include <math.h>

// Problem constants
#define BB 2
#define SS 2048
#define DD 1024
#define HH 16
#define HD 64
#define CC 16
#define BS (BB*SS)   // 4096 rows
#define BH (BB*HH)   // 32 batch-heads

// ---------------- device scratch (no allocations allowed) ----------------
__device__ float g_xn[BS*DD];        // LN(x)
__device__ float g_q[BH*SS*HD];
__device__ float g_k[BH*SS*HD];
__device__ float g_v[BH*SS*HD];
__device__ float g_att[BS*DD];       // attention output in [B,S,D] layout
__device__ float g_proj[BS*DD];      // att @ Wout^T + bout
__device__ float g_w[(size_t)BH*SS*SS]; // fallback w buffer if d_out is small

__device__ float c_h1[DD];
__device__ float c_cepre[DD];
__device__ float c_gate_a[HH];
__device__ float c_gate_v[HH];
__device__ float c_misc[2];          // [0]=temp, [1]=g mix
__device__ float c_alpha[HH];        // gate_a/(8*temp)
__device__ float c_beta[HH];         // bias_h/temp
__device__ float c_vadd[DD];         // sc*gate_v, broadcast add to v

// ---------------- chaos encoder, stage 1 (1 block) ----------------
__global__ void chaos1_kernel(const float* __restrict__ cf,
                              const float* __restrict__ W1, const float* __restrict__ b1,
                              const float* __restrict__ g1, const float* __restrict__ bb1,
                              const float* __restrict__ Wga, const float* __restrict__ bga,
                              const float* __restrict__ Wgv, const float* __restrict__ bgv,
                              const float* __restrict__ Wt,  const float* __restrict__ bt) {
    __shared__ float cfs[CC];
    __shared__ float red[256], red2[256];
    int t = threadIdx.x;
    if (t < CC) cfs[t] = cf[t];
    __syncthreads();

    if (t < HH) {
        float sa = bga[t], sv = bgv[t];
        #pragma unroll
        for (int c = 0; c < CC; c++) { sa += cfs[c]*Wga[t*CC+c]; sv += cfs[c]*Wgv[t*CC+c]; }
        c_gate_a[t] = 1.f/(1.f+expf(-sa));
        c_gate_v[t] = 1.f/(1.f+expf(-sv));
    } else if (t == 16) {
        float s = bt[0];
        #pragma unroll
        for (int c = 0; c < CC; c++) s += cfs[c]*Wt[c];
        float sp = (s > 20.f) ? s : log1pf(expf(s));
        c_misc[0] = sp + 1.0f;   // temp
    } else if (t == 17) {
        float s = 0.f;
        #pragma unroll
        for (int c = 0; c < CC; c++) s += cfs[c];
        s *= (1.0f/CC);
        c_misc[1] = (1.f/(1.f+expf(-s)))*0.5f + 0.5f;  // g
    }

    // h1_pre = cf @ W1^T + b1  (1024 outputs), then LN+ReLU
    float vals[4];
    float s1 = 0.f, s2 = 0.f;
    #pragma unroll
    for (int l = 0; l < 4; l++) {
        int i = t*4 + l;
        float a = b1[i];
        #pragma unroll
        for (int c = 0; c < CC; c++) a += cfs[c]*W1[i*CC+c];
        vals[l] = a; s1 += a; s2 += a*a;
    }
    red[t] = s1; red2[t] = s2; __syncthreads();
    for (int o = 128; o > 0; o >>= 1) {
        if (t < o) { red[t] += red[t+o]; red2[t] += red2[t+o]; }
        __syncthreads();
    }
    float m = red[0]*(1.0f/DD);
    float var = red2[0]*(1.0f/DD) - m*m;
    float inv = rsqrtf(var + 1e-5f);
    #pragma unroll
    for (int l = 0; l < 4; l++) {
        int i = t*4 + l;
        float h = (vals[l]-m)*inv*g1[i] + bb1[i];
        c_h1[i] = fmaxf(h, 0.f);
    }
}

// ---------------- chaos stage 2: ce_pre = h1 @ W2^T + b2 (64 blocks) -------
__global__ void chaos2_kernel(const float* __restrict__ W2, const float* __restrict__ b2) {
    __shared__ float h1s[DD];
    __shared__ float red[256];
    int t = threadIdx.x;
    #pragma unroll
    for (int l = 0; l < 4; l++) h1s[t + l*256] = c_h1[t + l*256];
    __syncthreads();
    int r = t >> 4, c = t & 15;
    int i = blockIdx.x*16 + r;
    float s = 0.f;
    for (int j = c; j < DD; j += 16) s += h1s[j]*W2[(size_t)i*DD + j];
    red[t] = s; __syncthreads();
    for (int o = 8; o > 0; o >>= 1) {
        if (c < o) red[t] += red[t+o];
        __syncthreads();
    }
    if (c == 0) c_cepre[i] = red[r*16] + b2[i];
}

// ---------------- chaos stage 3: LN(ce), sc, bias, alpha/beta, vadd --------
__global__ void chaos3_kernel(const float* __restrict__ g2, const float* __restrict__ bb2,
                              const float* __restrict__ qrot, const float* __restrict__ fscales) {
    __shared__ float ce[DD];
    __shared__ float scs[DD];
    __shared__ float red[256], red2[256];
    int t = threadIdx.x;
    float vals[4]; float s1 = 0.f, s2 = 0.f;
    #pragma unroll
    for (int l = 0; l < 4; l++) {
        int i = t + l*256;
        vals[l] = c_cepre[i]; s1 += vals[l]; s2 += vals[l]*vals[l];
    }
    red[t] = s1; red2[t] = s2; __syncthreads();
    for (int o = 128; o > 0; o >>= 1) {
        if (t < o) { red[t] += red[t+o]; red2[t] += red2[t+o]; }
        __syncthreads();
    }
    float m = red[0]*(1.0f/DD);
    float var = red2[0]*(1.0f/DD) - m*m;
    float inv = rsqrtf(var + 1e-5f);
    #pragma unroll
    for (int l = 0; l < 4; l++) {
        int i = t + l*256;
        ce[i] = (vals[l]-m)*inv*g2[i] + bb2[i];
    }
    __syncthreads();
    float sfs = 1.f/(1.f+expf(-fscales[0]));
    #pragma unroll
    for (int l = 0; l < 4; l++) {
        int i = t + l*256;
        int h = i >> 6, d = i & 63;
        float s = 0.f;
        #pragma unroll 8
        for (int e = 0; e < HD; e++) s += ce[h*HD+e]*qrot[e*HD+d];
        s *= sfs;
        scs[i] = s;
        c_vadd[i] = s * c_gate_v[h];
    }
    __syncthreads();
    if (t < HH) {
        float bsum = 0.f;
        for (int d = 0; d < HD; d++) bsum += scs[t*HD + d];
        float temp = c_misc[0];
        c_alpha[t] = c_gate_a[t]/(8.f*temp);
        c_beta[t]  = bsum/temp;
    }
}

// ---------------- LN-pre: xn = LN(x) (4096 blocks) ----------------
__global__ void ln_pre_kernel(const float* __restrict__ x,
                              const float* __restrict__ g, const float* __restrict__ b) {
    __shared__ float red[256], red2[256];
    size_t row = blockIdx.x;
    const float* xr = x + row*DD;
    float* o = g_xn + row*DD;
    int t = threadIdx.x;
    float vals[4]; float s1 = 0.f, s2 = 0.f;
    #pragma unroll
    for (int l = 0; l < 4; l++) {
        vals[l] = xr[t + l*256]; s1 += vals[l]; s2 += vals[l]*vals[l];
    }
    red[t] = s1; red2[t] = s2; __syncthreads();
    for (int off = 128; off > 0; off >>= 1) {
        if (t < off) { red[t] += red[t+off]; red2[t] += red2[t+off]; }
        __syncthreads();
    }
    float m = red[0]*(1.0f/DD);
    float var = red2[0]*(1.0f/DD) - m*m;
    float inv = rsqrtf(var + 1e-5f);
    #pragma unroll
    for (int l = 0; l < 4; l++) {
        int i = t + l*256;
        o[i] = (vals[l]-m)*inv*g[i] + b[i];
    }
}

// ---------------- QKV GEMM: [4096,3072] = xn[4096,1024] @ Wqkv^T ----------
__global__ __launch_bounds__(256) void sgemm_qkv_kernel(const float* __restrict__ Bw,
                                                        const float* __restrict__ bias) {
    __shared__ float As[16][65];
    __shared__ float Bs[16][65];
    int t = threadIdx.x;
    int tx = t & 15, ty = t >> 4;
    int m0 = blockIdx.y*64, n0 = blockIdx.x*64;
    float acc[4][4] = {};
    for (int k0 = 0; k0 < DD; k0 += 16) {
        #pragma unroll
        for (int l = 0; l < 4; l++) {
            int e = t + l*256;
            int r = e >> 4, kk = e & 15;
            As[kk][r] = g_xn[(size_t)(m0 + r)*DD + k0 + kk];
            Bs[kk][r] = Bw[(size_t)(n0 + r)*DD + k0 + kk];
        }
        __syncthreads();
        #pragma unroll
        for (int kk = 0; kk < 16; kk++) {
            float a[4], bv[4];
            #pragma unroll
            for (int i = 0; i < 4; i++) a[i] = As[kk][ty*4+i];
            #pragma unroll
            for (int j = 0; j < 4; j++) bv[j] = Bs[kk][tx*4+j];
            #pragma unroll
            for (int i = 0; i < 4; i++)
                #pragma unroll
                for (int j = 0; j < 4; j++)
                    acc[i][j] += a[i]*bv[j];
        }
        __syncthreads();
    }
    #pragma unroll
    for (int i = 0; i < 4; i++) {
        int m = m0 + ty*4 + i;
        int b = m >> 11, s = m & 2047;
        #pragma unroll
        for (int j = 0; j < 4; j++) {
            int n = n0 + tx*4 + j;
            float val = acc[i][j] + bias[n];
            int which = n >> 10, rest = n & 1023;
            int h = rest >> 6, dd = rest & 63;
            size_t dst = (((size_t)(b*HH + h))*SS + s)*HD + dd;
            if (which == 0)      g_q[dst] = val;
            else if (which == 1) g_k[dst] = val;
            else                 g_v[dst] = val + c_vadd[rest];
        }
    }
}

// ---------------- scores: w_pre = alpha[h]*q@k^T + beta[h], batched -------
__global__ __launch_bounds__(256) void sgemm_scores_kernel(float* __restrict__ wbuf) {
    __shared__ float As[16][65];
    __shared__ float Bs[16][65];
    int bh = blockIdx.z;
    const float* A = g_q + (size_t)bh*SS*HD;
    const float* Bm = g_k + (size_t)bh*SS*HD;
    int t = threadIdx.x;
    int tx = t & 15, ty = t >> 4;
    int m0 = blockIdx.y*64, n0 = blockIdx.x*64;
    float acc[4][4] = {};
    #pragma unroll
    for (int k0 = 0; k0 < HD; k0 += 16) {
        #pragma unroll
        for (int l = 0; l < 4; l++) {
            int e = t + l*256;
            int r = e >> 4, kk = e & 15;
            As[kk][r] = A[(size_t)(m0 + r)*HD + k0 + kk];
            Bs[kk][r] = Bm[(size_t)(n0 + r)*HD + k0 + kk];
        }
        __syncthreads();
        #pragma unroll
        for (int kk = 0; kk < 16; kk++) {
            float a[4], bv[4];
            #pragma unroll
            for (int i = 0; i < 4; i++) a[i] = As[kk][ty*4+i];
            #pragma unroll
            for (int j = 0; j < 4; j++) bv[j] = Bs[kk][tx*4+j];
            #pragma unroll
            for (int i = 0; i < 4; i++)
                #pragma unroll
                for (int j = 0; j < 4; j++)
                    acc[i][j] += a[i]*bv[j];
        }
        __syncthreads();
    }
    float al = c_alpha[bh & 15], be = c_beta[bh & 15];
    float* wrow = wbuf + (size_t)bh*SS*SS;
    #pragma unroll
    for (int i = 0; i < 4; i++) {
        int m = m0 + ty*4 + i;
        #pragma unroll
        for (int j = 0; j < 4; j++) {
            int n = n0 + tx*4 + j;
            wrow[(size_t)m*SS + n] = acc[i][j]*al + be;
        }
    }
}

// ---------------- softmax over rows of 2048 (65536 blocks) ----------------
__global__ void softmax_kernel(float* __restrict__ wbuf) {
    __shared__ float red[256];
    size_t row = blockIdx.x;
    float* p = wbuf + row*SS;
    int t = threadIdx.x;
    float v[8];
    float mx = -1e30f;
    #pragma unroll
    for (int l = 0; l < 8; l++) { v[l] = p[t + l*256]; mx = fmaxf(mx, v[l]); }
    red[t] = mx; __syncthreads();
    for (int o = 128; o > 0; o >>= 1) {
        if (t < o) red[t] = fmaxf(red[t], red[t+o]);
        __syncthreads();
    }
    float mxv = red[0]; __syncthreads();
    float s = 0.f;
    #pragma unroll
    for (int l = 0; l < 8; l++) { v[l] = expf(v[l] - mxv); s += v[l]; }
    red[t] = s; __syncthreads();
    for (int o = 128; o > 0; o >>= 1) {
        if (t < o) red[t] += red[t+o];
        __syncthreads();
    }
    float inv = 1.f/red[0];
    #pragma unroll
    for (int l = 0; l < 8; l++) p[t + l*256] = v[l]*inv;
}

// ---------------- att = w @ v, batched NN, writes [B,S,D] ----------------
__global__ __launch_bounds__(256) void sgemm_att_kernel(const float* __restrict__ wbuf) {
    __shared__ float As[16][65];
    __shared__ float Bs[16][65];
    int bh = blockIdx.z;
    int b = bh >> 4, h = bh & 15;
    const float* A = wbuf + (size_t)bh*SS*SS;   // [2048 x 2048]
    const float* Bv = g_v + (size_t)bh*SS*HD;   // [2048 x 64]
    int t = threadIdx.x;
    int tx = t & 15, ty = t >> 4;
    int m0 = blockIdx.y*64;                     // n0 == 0, N = 64
    float acc[4][4] = {};
    for (int k0 = 0; k0 < SS; k0 += 16) {
        #pragma unroll
        for (int l = 0; l < 4; l++) {
            int e = t + l*256;
            int r = e >> 4, kk = e & 15;
            As[kk][r] = A[(size_t)(m0 + r)*SS + k0 + kk];
            int kk2 = e >> 6, c2 = e & 63;
            Bs[kk2][c2] = Bv[(size_t)(k0 + kk2)*HD + c2];
        }
        __syncthreads();
        #pragma unroll
        for (int kk = 0; kk < 16; kk++) {
            float a[4], bv[4];
            #pragma unroll
            for (int i = 0; i < 4; i++) a[i] = As[kk][ty*4+i];
            #pragma unroll
            for (int j = 0; j < 4; j++) bv[j] = Bs[kk][tx*4+j];
            #pragma unroll
            for (int i = 0; i < 4; i++)
                #pragma unroll
                for (int j = 0; j < 4; j++)
                    acc[i][j] += a[i]*bv[j];
        }
        __syncthreads();
    }
    #pragma unroll
    for (int i = 0; i < 4; i++) {
        int m = m0 + ty*4 + i;
        #pragma unroll
        for (int j = 0; j < 4; j++) {
            int dd = tx*4 + j;
            g_att[((size_t)(b*SS + m))*DD + h*HD + dd] = acc[i][j];
        }
    }
}

// ---------------- out = att @ Wout^T + bout -> g_proj ----------------
__global__ __launch_bounds__(256) void sgemm_out_kernel(const float* __restrict__ Bw,
                                                        const float* __restrict__ bias) {
    __shared__ float As[16][65];
    __shared__ float Bs[16][65];
    int t = threadIdx.x;
    int tx = t & 15, ty = t >> 4;
    int m0 = blockIdx.y*64, n0 = blockIdx.x*64;
    float acc[4][4] = {};
    for (int k0 = 0; k0 < DD; k0 += 16) {
        #pragma unroll
        for (int l = 0; l < 4; l++) {
            int e = t + l*256;
            int r = e >> 4, kk = e & 15;
            As[kk][r] = g_att[(size_t)(m0 + r)*DD + k0 + kk];
            Bs[kk][r] = Bw[(size_t)(n0 + r)*DD + k0 + kk];
        }
        __syncthreads();
        #pragma unroll
        for (int kk = 0; kk < 16; kk++) {
            float a[4], bv[4];
            #pragma unroll
            for (int i = 0; i < 4; i++) a[i] = As[kk][ty*4+i];
            #pragma unroll
            for (int j = 0; j < 4; j++) bv[j] = Bs[kk][tx*4+j];
            #pragma unroll
            for (int i = 0; i < 4; i++)
                #pragma unroll
                for (int j = 0; j < 4; j++)
                    acc[i][j] += a[i]*bv[j];
        }
        __syncthreads();
    }
    #pragma unroll
    for (int i = 0; i < 4; i++) {
        int m = m0 + ty*4 + i;
        #pragma unroll
        for (int j = 0; j < 4; j++) {
            int n = n0 + tx*4 + j;
            g_proj[(size_t)m*DD + n] = acc[i][j] + bias[n];
        }
    }
}

// ---------------- final: mix + LN-post -> d_out[0 : BS*D] ----------------
__global__ void final_kernel(const float* __restrict__ g, const float* __restrict__ b,
                             float* __restrict__ out) {
    __shared__ float red[256], red2[256];
    size_t row = blockIdx.x;
    int t = threadIdx.x;
    float gm = c_misc[1];
    float vals[4]; float s1 = 0.f, s2 = 0.f;
    #pragma unroll
    for (int l = 0; l < 4; l++) {
        size_t idx = row*DD + t + l*256;
        float vv = g_proj[idx]*gm + g_xn[idx]*(1.f - gm);
        vals[l] = vv; s1 += vv; s2 += vv*vv;
    }
    red[t] = s1; red2[t] = s2; __syncthreads();
    for (int off = 128; off > 0; off >>= 1) {
        if (t < off) { red[t] += red[t+off]; red2[t] += red2[t+off]; }
        __syncthreads();
    }
    float m = red[0]*(1.0f/DD);
    float var = red2[0]*(1.0f/DD) - m*m;
    float inv = rsqrtf(var + 1e-5f);
    #pragma unroll
    for (int l = 0; l < 4; l++) {
        int i = t + l*256;
        out[row*DD + i] = (vals[l]-m)*inv*g[i] + b[i];
    }
}

// ---------------------------------------------------------------------------
extern "C" void kernel_launch(void* const* d_in, const int* in_sizes, int n_in,
                              void* d_out, int out_size) {
    const float* x      = (const float*)d_in[0];
    const float* cf     = (const float*)d_in[1];
    const float* lnpg   = (const float*)d_in[2];
    const float* lnpb   = (const float*)d_in[3];
    const float* Wqkv   = (const float*)d_in[4];
    const float* bqkv   = (const float*)d_in[5];
    const float* eW1    = (const float*)d_in[6];
    const float* eb1    = (const float*)d_in[7];
    const float* eg1    = (const float*)d_in[8];
    const float* ebb1   = (const float*)d_in[9];
    const float* eW2    = (const float*)d_in[10];
    const float* eb2    = (const float*)d_in[11];
    const float* eg2    = (const float*)d_in[12];
    const float* ebb2   = (const float*)d_in[13];
    const float* Wga    = (const float*)d_in[14];
    const float* bga    = (const float*)d_in[15];
    const float* Wgv    = (const float*)d_in[16];
    const float* bgv    = (const float*)d_in[17];
    const float* Wt     = (const float*)d_in[18];
    const float* bt     = (const float*)d_in[19];
    const float* qrot   = (const float*)d_in[20];
    const float* fsc    = (const float*)d_in[21];
    const float* Wout   = (const float*)d_in[22];
    const float* bout   = (const float*)d_in[23];
    const float* lnqg   = (const float*)d_in[24];
    const float* lnqb   = (const float*)d_in[25];

    float* out = (float*)d_out;

    // w is the second returned tensor: lives in d_out after the LN output if
    // the harness concatenated both outputs; otherwise fall back to scratch.
    size_t need = (size_t)BS*DD + (size_t)BH*SS*SS;
    float* wbuf;
    if ((size_t)out_size >= need) {
        wbuf = out + (size_t)BS*DD;
    } else {
        float* wptr = nullptr;
        cudaGetSymbolAddress((void**)&wptr, g_w);
        wbuf = wptr;
    }

    chaos1_kernel<<<1, 256>>>(cf, eW1, eb1, eg1, ebb1, Wga, bga, Wgv, bgv, Wt, bt);
    chaos2_kernel<<<64, 256>>>(eW2, eb2);
    chaos3_kernel<<<1, 256>>>(eg2, ebb2, qrot, fsc);

    ln_pre_kernel<<<BS, 256>>>(x, lnpg, lnpb);

    // QKV: M=4096, N=3072
    sgemm_qkv_kernel<<<dim3(3*DD/64, BS/64), 256>>>(Wqkv, bqkv);

    // scores: per (b,h) 2048x2048, K=64
    sgemm_scores_kernel<<<dim3(SS/64, SS/64, BH), 256>>>(wbuf);

    // softmax rows
    softmax_kernel<<<BH*SS, 256>>>(wbuf);

    // att = w @ v : per (b,h) 2048x64, K=2048
    sgemm_att_kernel<<<dim3(1, SS/64, BH), 256>>>(wbuf);

    // out projection: M=4096, N=1024
    sgemm_out_kernel<<<dim3(DD/64, BS/64), 256>>>(Wout, bout);

    // final mix + LN-post
    final_kernel<<<BS, 256>>>(lnqg, lnqb, out);
}

// round 2
// speedup vs baseline: 3.2003x; 3.2003x over previous
#include <cuda_runtime.h>
#include <math.h>
#include <stdint.h>

// Problem constants
#define BB 2
#define SS 2048
#define DD 1024
#define HH 16
#define HD 64
#define CC 16
#define BS (BB*SS)   // 4096 rows
#define BH (BB*HH)   // 32 batch-heads

// ---------------- device scratch (no allocations allowed) ----------------
__device__ float g_xn[BS*DD];        // LN(x)
__device__ float g_q[BH*SS*HD];
__device__ float g_k[BH*SS*HD];
__device__ float g_v[BH*SS*HD];
__device__ float g_att[BS*DD];       // attention output in [B,S,D] layout
__device__ float g_proj[BS*DD];      // att @ Wout^T + bout
__device__ float g_w[(size_t)BH*SS*SS]; // fallback w buffer if d_out is small

__device__ float c_h1[DD];
__device__ float c_cepre[DD];
__device__ float c_gate_a[HH];
__device__ float c_gate_v[HH];
__device__ float c_misc[2];          // [0]=temp, [1]=g mix
__device__ float c_alpha[HH];        // gate_a/(8*temp)
__device__ float c_beta[HH];         // bias_h/temp
__device__ float c_vadd[DD];         // sc*gate_v, broadcast add to v

// ---------------- helpers ----------------
__device__ __forceinline__ float to_tf32(float x) {
    float y;
    asm("cvt.rna.tf32.f32 %0, %1;" : "=f"(y) : "f"(x));
    return y;
}

// fast exp on FMA pipe: exp(x) = 2^(x*log2e); poly on [-0.5,0.5] + exponent inject
__device__ __forceinline__ float fast_exp(float x) {
    const float LOG2E = 1.4426950408889634f;
    float y = x * LOG2E;
    float z = y + 12582912.0f;            // round-to-nearest integer (2^23*1.5 magic)
    int   i = __float_as_int(z);           // integer part in low mantissa bits
    float fl = z - 12582912.0f;
    float f = y - fl;                      // f in [-0.5, 0.5]
    // 2^f Taylor degree 6 (rel err ~2e-7 on [-0.5,0.5])
    float p = 1.5252734e-5f;
    p = fmaf(p, f, 1.3333558e-4f);
    p = fmaf(p, f, 1.3333558e-3f);
    p = fmaf(p, f, 9.6181298e-3f);
    p = fmaf(p, f, 5.5504109e-2f);
    p = fmaf(p, f, 2.4022651e-1f);
    p = fmaf(p, f, 6.9314718e-1f);
    p = fmaf(p, f, 1.0f);
    return __int_as_float(__float_as_int(p) + (i << 23));
}

// ---------------- chaos encoder, stage 1 (1 block) ----------------
__global__ void chaos1_kernel(const float* __restrict__ cf,
                              const float* __restrict__ W1, const float* __restrict__ b1,
                              const float* __restrict__ g1, const float* __restrict__ bb1,
                              const float* __restrict__ Wga, const float* __restrict__ bga,
                              const float* __restrict__ Wgv, const float* __restrict__ bgv,
                              const float* __restrict__ Wt,  const float* __restrict__ bt) {
    __shared__ float cfs[CC];
    __shared__ float red[256], red2[256];
    int t = threadIdx.x;
    if (t < CC) cfs[t] = cf[t];
    __syncthreads();

    if (t < HH) {
        float sa = bga[t], sv = bgv[t];
        #pragma unroll
        for (int c = 0; c < CC; c++) { sa += cfs[c]*Wga[t*CC+c]; sv += cfs[c]*Wgv[t*CC+c]; }
        c_gate_a[t] = 1.f/(1.f+expf(-sa));
        c_gate_v[t] = 1.f/(1.f+expf(-sv));
    } else if (t == 16) {
        float s = bt[0];
        #pragma unroll
        for (int c = 0; c < CC; c++) s += cfs[c]*Wt[c];
        float sp = (s > 20.f) ? s : log1pf(expf(s));
        c_misc[0] = sp + 1.0f;   // temp
    } else if (t == 17) {
        float s = 0.f;
        #pragma unroll
        for (int c = 0; c < CC; c++) s += cfs[c];
        s *= (1.0f/CC);
        c_misc[1] = (1.f/(1.f+expf(-s)))*0.5f + 0.5f;  // g
    }

    float vals[4];
    float s1 = 0.f, s2 = 0.f;
    #pragma unroll
    for (int l = 0; l < 4; l++) {
        int i = t*4 + l;
        float a = b1[i];
        #pragma unroll
        for (int c = 0; c < CC; c++) a += cfs[c]*W1[i*CC+c];
        vals[l] = a; s1 += a; s2 += a*a;
    }
    red[t] = s1; red2[t] = s2; __syncthreads();
    for (int o = 128; o > 0; o >>= 1) {
        if (t < o) { red[t] += red[t+o]; red2[t] += red2[t+o]; }
        __syncthreads();
    }
    float m = red[0]*(1.0f/DD);
    float var = red2[0]*(1.0f/DD) - m*m;
    float inv = rsqrtf(var + 1e-5f);
    #pragma unroll
    for (int l = 0; l < 4; l++) {
        int i = t*4 + l;
        float h = (vals[l]-m)*inv*g1[i] + bb1[i];
        c_h1[i] = fmaxf(h, 0.f);
    }
}

// ---------------- chaos stage 2: ce_pre = h1 @ W2^T + b2 (64 blocks) -------
__global__ void chaos2_kernel(const float* __restrict__ W2, const float* __restrict__ b2) {
    __shared__ float h1s[DD];
    __shared__ float red[256];
    int t = threadIdx.x;
    #pragma unroll
    for (int l = 0; l < 4; l++) h1s[t + l*256] = c_h1[t + l*256];
    __syncthreads();
    int r = t >> 4, c = t & 15;
    int i = blockIdx.x*16 + r;
    float s = 0.f;
    for (int j = c; j < DD; j += 16) s += h1s[j]*W2[(size_t)i*DD + j];
    red[t] = s; __syncthreads();
    for (int o = 8; o > 0; o >>= 1) {
        if (c < o) red[t] += red[t+o];
        __syncthreads();
    }
    if (c == 0) c_cepre[i] = red[r*16] + b2[i];
}

// ---------------- chaos stage 3 ----------------
__global__ void chaos3_kernel(const float* __restrict__ g2, const float* __restrict__ bb2,
                              const float* __restrict__ qrot, const float* __restrict__ fscales) {
    __shared__ float ce[DD];
    __shared__ float scs[DD];
    __shared__ float red[256], red2[256];
    int t = threadIdx.x;
    float vals[4]; float s1 = 0.f, s2 = 0.f;
    #pragma unroll
    for (int l = 0; l < 4; l++) {
        int i = t + l*256;
        vals[l] = c_cepre[i]; s1 += vals[l]; s2 += vals[l]*vals[l];
    }
    red[t] = s1; red2[t] = s2; __syncthreads();
    for (int o = 128; o > 0; o >>= 1) {
        if (t < o) { red[t] += red[t+o]; red2[t] += red2[t+o]; }
        __syncthreads();
    }
    float m = red[0]*(1.0f/DD);
    float var = red2[0]*(1.0f/DD) - m*m;
    float inv = rsqrtf(var + 1e-5f);
    #pragma unroll
    for (int l = 0; l < 4; l++) {
        int i = t + l*256;
        ce[i] = (vals[l]-m)*inv*g2[i] + bb2[i];
    }
    __syncthreads();
    float sfs = 1.f/(1.f+expf(-fscales[0]));
    #pragma unroll
    for (int l = 0; l < 4; l++) {
        int i = t + l*256;
        int h = i >> 6, d = i & 63;
        float s = 0.f;
        #pragma unroll 8
        for (int e = 0; e < HD; e++) s += ce[h*HD+e]*qrot[e*HD+d];
        s *= sfs;
        scs[i] = s;
        c_vadd[i] = s * c_gate_v[h];
    }
    __syncthreads();
    if (t < HH) {
        float bsum = 0.f;
        for (int d = 0; d < HD; d++) bsum += scs[t*HD + d];
        float temp = c_misc[0];
        c_alpha[t] = c_gate_a[t]/(8.f*temp);
        c_beta[t]  = bsum/temp;
    }
}

// ---------------- LN-pre ----------------
__global__ void ln_pre_kernel(const float* __restrict__ x,
                              const float* __restrict__ g, const float* __restrict__ b) {
    __shared__ float red[256], red2[256];
    size_t row = blockIdx.x;
    const float* xr = x + row*DD;
    float* o = g_xn + row*DD;
    int t = threadIdx.x;
    float vals[4]; float s1 = 0.f, s2 = 0.f;
    #pragma unroll
    for (int l = 0; l < 4; l++) {
        vals[l] = xr[t + l*256]; s1 += vals[l]; s2 += vals[l]*vals[l];
    }
    red[t] = s1; red2[t] = s2; __syncthreads();
    for (int off = 128; off > 0; off >>= 1) {
        if (t < off) { red[t] += red[t+off]; red2[t] += red2[t+off]; }
        __syncthreads();
    }
    float m = red[0]*(1.0f/DD);
    float var = red2[0]*(1.0f/DD) - m*m;
    float inv = rsqrtf(var + 1e-5f);
    #pragma unroll
    for (int l = 0; l < 4; l++) {
        int i = t + l*256;
        o[i] = (vals[l]-m)*inv*g[i] + b[i];
    }
}

// ============================================================================
// Templated tf32 tensor-core GEMM.
//  C[M,N] = A[M,K] (row-major, K inner) x B (NT: [N,K] row-major; NN: [K,N])
//  BM=128, BK=32, 256 threads (8 warps as 4x2), warp tile 32 x WN.
//  Smem: A and NT-B stored [row][k] with XOR-swizzle (conflict-free both ways).
//        NN-B stored [k][n] with pad 4 (conflict-free).
// ============================================================================

struct EpiQKV {
    const float* bias;
    __device__ __forceinline__ void init(int) {}
    __device__ __forceinline__ void write(int m, int n, float v) const {
        float val = v + bias[n];
        int b = m >> 11, s = m & 2047;
        int which = n >> 10, rest = n & 1023;
        size_t dst = (((size_t)(b*HH + (rest >> 6)))*SS + s)*HD + (rest & 63);
        if (which == 0)      g_q[dst] = val;
        else if (which == 1) g_k[dst] = val;
        else                 g_v[dst] = val + c_vadd[rest];
    }
};

struct EpiScores {
    float* w;
    float al, be;
    __device__ __forceinline__ void init(int bh) {
        al = c_alpha[bh & 15]; be = c_beta[bh & 15];
        w += (size_t)bh*SS*SS;
    }
    __device__ __forceinline__ void write(int m, int n, float v) const {
        w[(size_t)m*SS + n] = v*al + be;
    }
};

struct EpiPV {
    size_t base;
    __device__ __forceinline__ void init(int bh) {
        base = ((size_t)(bh >> 4)*SS)*DD + (size_t)(bh & 15)*HD;
    }
    __device__ __forceinline__ void write(int m, int n, float v) const {
        g_att[base + (size_t)m*DD + n] = v;
    }
};

struct EpiOut {
    const float* bias;
    __device__ __forceinline__ void init(int) {}
    __device__ __forceinline__ void write(int m, int n, float v) const {
        g_proj[(size_t)m*DD + n] = v + bias[n];
    }
};

template<int BN, int WN, bool BNT, typename Epi>
__global__ __launch_bounds__(256, 2) void mma_gemm(
    const float* __restrict__ A, int lda, size_t sA,
    const float* __restrict__ B, int ldb, size_t sB,
    int K, Epi epi)
{
    constexpr int BM = 128, BK = 32;
    constexpr int NI = WN / 8;
    constexpr int BS_SZ = BNT ? (BN*BK) : (BK*(BN+4));
    __shared__ float As[BM*BK];
    __shared__ float Bs[BS_SZ];

    int t = threadIdx.x;
    int lane = t & 31, warp = t >> 5;
    int q = lane >> 2, r = lane & 3;
    int wm = (warp >> 1) * 32;
    int wn = (warp & 1) * WN;
    int m0 = blockIdx.y * BM, n0 = blockIdx.x * BN;
    int bh = blockIdx.z;
    A += (size_t)bh * sA;
    B += (size_t)bh * sB;
    epi.init(bh);

    float acc[2][NI][4];
    #pragma unroll
    for (int mi = 0; mi < 2; mi++)
        #pragma unroll
        for (int nj = 0; nj < NI; nj++)
            #pragma unroll
            for (int p = 0; p < 4; p++) acc[mi][nj][p] = 0.f;

    for (int k0 = 0; k0 < K; k0 += BK) {
        // ---- copy A tile: [BM][BK] global (k inner) -> swizzled smem ----
        #pragma unroll
        for (int i = 0; i < BM*BK/1024; i++) {
            int f = t + i*256;
            int row = f >> 3, k4 = f & 7;
            float4 v = *(const float4*)(A + (size_t)(m0+row)*lda + k0 + k4*4);
            v.x = to_tf32(v.x); v.y = to_tf32(v.y); v.z = to_tf32(v.z); v.w = to_tf32(v.w);
            *(float4*)&As[row*32 + ((k4 ^ (row & 7)) << 2)] = v;
        }
        // ---- copy B tile ----
        if (BNT) {
            #pragma unroll
            for (int i = 0; i < BN*BK/1024; i++) {
                int f = t + i*256;
                int row = f >> 3, k4 = f & 7;
                float4 v = *(const float4*)(B + (size_t)(n0+row)*ldb + k0 + k4*4);
                v.x = to_tf32(v.x); v.y = to_tf32(v.y); v.z = to_tf32(v.z); v.w = to_tf32(v.w);
                *(float4*)&Bs[row*32 + ((k4 ^ (row & 7)) << 2)] = v;
            }
        } else {
            #pragma unroll
            for (int i = 0; i < BK*BN/1024; i++) {
                int f = t + i*256;
                int kk = f / (BN/4), n4 = f % (BN/4);
                float4 v = *(const float4*)(B + (size_t)(k0+kk)*ldb + n0 + n4*4);
                v.x = to_tf32(v.x); v.y = to_tf32(v.y); v.z = to_tf32(v.z); v.w = to_tf32(v.w);
                *(float4*)&Bs[kk*(BN+4) + n4*4] = v;
            }
        }
        __syncthreads();

        #pragma unroll
        for (int ks = 0; ks < 4; ks++) {
            uint32_t af[2][4];
            #pragma unroll
            for (int mi = 0; mi < 2; mi++) {
                #pragma unroll
                for (int p = 0; p < 4; p++) {
                    int row = wm + mi*16 + q + ((p & 1) << 3);
                    int kk  = ks*8 + r + ((p >> 1) << 2);
                    af[mi][p] = __float_as_uint(
                        As[row*32 + (((kk >> 2) ^ (row & 7)) << 2) + (kk & 3)]);
                }
            }
            uint32_t bf[NI][2];
            #pragma unroll
            for (int nj = 0; nj < NI; nj++) {
                int col = wn + nj*8 + q;
                #pragma unroll
                for (int p = 0; p < 2; p++) {
                    int kk = ks*8 + r + p*4;
                    if (BNT)
                        bf[nj][p] = __float_as_uint(
                            Bs[col*32 + (((kk >> 2) ^ (col & 7)) << 2) + (kk & 3)]);
                    else
                        bf[nj][p] = __float_as_uint(Bs[kk*(BN+4) + col]);
                }
            }
            #pragma unroll
            for (int mi = 0; mi < 2; mi++)
                #pragma unroll
                for (int nj = 0; nj < NI; nj++) {
                    asm volatile(
                        "mma.sync.aligned.m16n8k8.row.col.f32.tf32.tf32.f32 "
                        "{%0,%1,%2,%3}, {%4,%5,%6,%7}, {%8,%9}, {%0,%1,%2,%3};"
                        : "+f"(acc[mi][nj][0]), "+f"(acc[mi][nj][1]),
                          "+f"(acc[mi][nj][2]), "+f"(acc[mi][nj][3])
                        : "r"(af[mi][0]), "r"(af[mi][1]), "r"(af[mi][2]), "r"(af[mi][3]),
                          "r"(bf[nj][0]), "r"(bf[nj][1]));
                }
        }
        __syncthreads();
    }

    // ---- epilogue ----
    #pragma unroll
    for (int mi = 0; mi < 2; mi++)
        #pragma unroll
        for (int nj = 0; nj < NI; nj++)
            #pragma unroll
            for (int p = 0; p < 4; p++) {
                int m = m0 + wm + mi*16 + q + ((p >> 1) << 3);
                int n = n0 + wn + nj*8 + 2*r + (p & 1);
                epi.write(m, n, acc[mi][nj][p]);
            }
}

// ---------------- softmax over rows of 2048 ----------------
__global__ void softmax_kernel(float* __restrict__ wbuf) {
    __shared__ float red[256];
    size_t row = blockIdx.x;
    float4* p = reinterpret_cast<float4*>(wbuf + row*SS);
    int t = threadIdx.x;
    float4 v[2];
    float mx = -1e30f;
    #pragma unroll
    for (int l = 0; l < 2; l++) {
        v[l] = p[t + l*256];
        mx = fmaxf(mx, fmaxf(fmaxf(v[l].x, v[l].y), fmaxf(v[l].z, v[l].w)));
    }
    red[t] = mx; __syncthreads();
    for (int o = 128; o > 0; o >>= 1) {
        if (t < o) red[t] = fmaxf(red[t], red[t+o]);
        __syncthreads();
    }
    float mxv = red[0]; __syncthreads();
    float s = 0.f;
    #pragma unroll
    for (int l = 0; l < 2; l++) {
        v[l].x = fast_exp(v[l].x - mxv);
        v[l].y = fast_exp(v[l].y - mxv);
        v[l].z = fast_exp(v[l].z - mxv);
        v[l].w = fast_exp(v[l].w - mxv);
        s += (v[l].x + v[l].y) + (v[l].z + v[l].w);
    }
    red[t] = s; __syncthreads();
    for (int o = 128; o > 0; o >>= 1) {
        if (t < o) red[t] += red[t+o];
        __syncthreads();
    }
    float inv = 1.f/red[0];
    #pragma unroll
    for (int l = 0; l < 2; l++) {
        v[l].x *= inv; v[l].y *= inv; v[l].z *= inv; v[l].w *= inv;
        p[t + l*256] = v[l];
    }
}

// ---------------- final: mix + LN-post ----------------
__global__ void final_kernel(const float* __restrict__ g, const float* __restrict__ b,
                             float* __restrict__ out) {
    __shared__ float red[256], red2[256];
    size_t row = blockIdx.x;
    int t = threadIdx.x;
    float gm = c_misc[1];
    float vals[4]; float s1 = 0.f, s2 = 0.f;
    #pragma unroll
    for (int l = 0; l < 4; l++) {
        size_t idx = row*DD + t + l*256;
        float vv = g_proj[idx]*gm + g_xn[idx]*(1.f - gm);
        vals[l] = vv; s1 += vv; s2 += vv*vv;
    }
    red[t] = s1; red2[t] = s2; __syncthreads();
    for (int off = 128; off > 0; off >>= 1) {
        if (t < off) { red[t] += red[t+off]; red2[t] += red2[t+off]; }
        __syncthreads();
    }
    float m = red[0]*(1.0f/DD);
    float var = red2[0]*(1.0f/DD) - m*m;
    float inv = rsqrtf(var + 1e-5f);
    #pragma unroll
    for (int l = 0; l < 4; l++) {
        int i = t + l*256;
        out[row*DD + i] = (vals[l]-m)*inv*g[i] + b[i];
    }
}

// ---------------------------------------------------------------------------
extern "C" void kernel_launch(void* const* d_in, const int* in_sizes, int n_in,
                              void* d_out, int out_size) {
    const float* x      = (const float*)d_in[0];
    const float* cf     = (const float*)d_in[1];
    const float* lnpg   = (const float*)d_in[2];
    const float* lnpb   = (const float*)d_in[3];
    const float* Wqkv   = (const float*)d_in[4];
    const float* bqkv   = (const float*)d_in[5];
    const float* eW1    = (const float*)d_in[6];
    const float* eb1    = (const float*)d_in[7];
    const float* eg1    = (const float*)d_in[8];
    const float* ebb1   = (const float*)d_in[9];
    const float* eW2    = (const float*)d_in[10];
    const float* eb2    = (const float*)d_in[11];
    const float* eg2    = (const float*)d_in[12];
    const float* ebb2   = (const float*)d_in[13];
    const float* Wga    = (const float*)d_in[14];
    const float* bga    = (const float*)d_in[15];
    const float* Wgv    = (const float*)d_in[16];
    const float* bgv    = (const float*)d_in[17];
    const float* Wt     = (const float*)d_in[18];
    const float* bt     = (const float*)d_in[19];
    const float* qrot   = (const float*)d_in[20];
    const float* fsc    = (const float*)d_in[21];
    const float* Wout   = (const float*)d_in[22];
    const float* bout   = (const float*)d_in[23];
    const float* lnqg   = (const float*)d_in[24];
    const float* lnqb   = (const float*)d_in[25];

    float* out = (float*)d_out;

    size_t need = (size_t)BS*DD + (size_t)BH*SS*SS;
    float* wbuf;
    if ((size_t)out_size >= need) {
        wbuf = out + (size_t)BS*DD;
    } else {
        float* wptr = nullptr;
        cudaGetSymbolAddress((void**)&wptr, g_w);
        wbuf = wptr;
    }

    float *xn_p, *q_p, *k_p, *v_p, *att_p;
    cudaGetSymbolAddress((void**)&xn_p,  g_xn);
    cudaGetSymbolAddress((void**)&q_p,   g_q);
    cudaGetSymbolAddress((void**)&k_p,   g_k);
    cudaGetSymbolAddress((void**)&v_p,   g_v);
    cudaGetSymbolAddress((void**)&att_p, g_att);

    chaos1_kernel<<<1, 256>>>(cf, eW1, eb1, eg1, ebb1, Wga, bga, Wgv, bgv, Wt, bt);
    chaos2_kernel<<<64, 256>>>(eW2, eb2);
    chaos3_kernel<<<1, 256>>>(eg2, ebb2, qrot, fsc);

    ln_pre_kernel<<<BS, 256>>>(x, lnpg, lnpb);

    // QKV: C[4096,3072] = xn @ Wqkv^T (NT)
    mma_gemm<128, 64, true><<<dim3(3*DD/128, BS/128, 1), 256>>>(
        xn_p, DD, 0, Wqkv, DD, 0, DD, EpiQKV{bqkv});

    // scores: per bh, C[2048,2048] = q @ k^T (NT), K=64
    mma_gemm<128, 64, true><<<dim3(SS/128, SS/128, BH), 256>>>(
        q_p, HD, (size_t)SS*HD, k_p, HD, (size_t)SS*HD, HD, EpiScores{wbuf, 0.f, 0.f});

    // softmax rows
    softmax_kernel<<<BH*SS, 256>>>(wbuf);

    // att = w @ v (NN), per bh: C[2048,64], K=2048
    mma_gemm<64, 32, false><<<dim3(1, SS/128, BH), 256>>>(
        wbuf, SS, (size_t)SS*SS, v_p, HD, (size_t)SS*HD, SS, EpiPV{0});

    // out projection: C[4096,1024] = att @ Wout^T (NT)
    mma_gemm<128, 64, true><<<dim3(DD/128, BS/128, 1), 256>>>(
        att_p, DD, 0, Wout, DD, 0, DD, EpiOut{bout});

    final_kernel<<<BS, 256>>>(lnqg, lnqb, out);
}

// round 3
// speedup vs baseline: 3.8776x; 1.2117x over previous
#include <cuda_runtime.h>
#include <math.h>
#include <stdint.h>

#define BB 2
#define SS 2048
#define DD 1024
#define HH 16
#define HD 64
#define CC 16
#define BS (BB*SS)
#define BH (BB*HH)

// ---------------- device scratch ----------------
__device__ __align__(256) float g_xn[BS*DD];
__device__ __align__(256) float g_q[BH*SS*HD];
__device__ __align__(256) float g_k[BH*SS*HD];
__device__ __align__(256) float g_v[BH*SS*HD];
__device__ __align__(256) float g_att[BS*DD];
__device__ __align__(256) float g_proj[BS*DD];
__device__ __align__(256) float g_w[(size_t)BH*SS*SS];

__device__ float c_h1[DD];
__device__ float c_cepre[DD];
__device__ float c_gate_a[HH];
__device__ float c_gate_v[HH];
__device__ float c_misc[2];
__device__ float c_alpha[HH];
__device__ float c_beta[HH];
__device__ float c_vadd[DD];

// ---------------- helpers ----------------
__device__ __forceinline__ float to_tf32(float x) {
    float y;
    asm("cvt.rna.tf32.f32 %0, %1;" : "=f"(y) : "f"(x));
    return y;
}

__device__ __forceinline__ float fast_exp(float x) {
    const float LOG2E = 1.4426950408889634f;
    float y = x * LOG2E;
    float z = y + 12582912.0f;
    int   i = __float_as_int(z);
    float fl = z - 12582912.0f;
    float f = y - fl;
    float p = 1.5252734e-5f;
    p = fmaf(p, f, 1.3333558e-4f);
    p = fmaf(p, f, 1.3333558e-3f);
    p = fmaf(p, f, 9.6181298e-3f);
    p = fmaf(p, f, 5.5504109e-2f);
    p = fmaf(p, f, 2.4022651e-1f);
    p = fmaf(p, f, 6.9314718e-1f);
    p = fmaf(p, f, 1.0f);
    return __int_as_float(__float_as_int(p) + (i << 23));
}

__device__ __forceinline__ void mma_tf32(float c[4], const uint32_t a[4],
                                         uint32_t b0, uint32_t b1) {
    asm volatile(
        "mma.sync.aligned.m16n8k8.row.col.f32.tf32.tf32.f32 "
        "{%0,%1,%2,%3}, {%4,%5,%6,%7}, {%8,%9}, {%0,%1,%2,%3};"
        : "+f"(c[0]), "+f"(c[1]), "+f"(c[2]), "+f"(c[3])
        : "r"(a[0]), "r"(a[1]), "r"(a[2]), "r"(a[3]), "r"(b0), "r"(b1));
}

__device__ __forceinline__ void cp16(float* dst, const float* src) {
    unsigned d = (unsigned)__cvta_generic_to_shared(dst);
    asm volatile("cp.async.cg.shared.global [%0], [%1], 16;" :: "r"(d), "l"(src));
}
__device__ __forceinline__ void cp_commit() { asm volatile("cp.async.commit_group;"); }
__device__ __forceinline__ void cp_wait1() { asm volatile("cp.async.wait_group 1;"); }
__device__ __forceinline__ void cp_wait0() { asm volatile("cp.async.wait_group 0;"); }

// ---------------- chaos encoder, stage 1 ----------------
__global__ void chaos1_kernel(const float* __restrict__ cf,
                              const float* __restrict__ W1, const float* __restrict__ b1,
                              const float* __restrict__ g1, const float* __restrict__ bb1,
                              const float* __restrict__ Wga, const float* __restrict__ bga,
                              const float* __restrict__ Wgv, const float* __restrict__ bgv,
                              const float* __restrict__ Wt,  const float* __restrict__ bt) {
    __shared__ float cfs[CC];
    __shared__ float red[256], red2[256];
    int t = threadIdx.x;
    if (t < CC) cfs[t] = cf[t];
    __syncthreads();

    if (t < HH) {
        float sa = bga[t], sv = bgv[t];
        #pragma unroll
        for (int c = 0; c < CC; c++) { sa += cfs[c]*Wga[t*CC+c]; sv += cfs[c]*Wgv[t*CC+c]; }
        c_gate_a[t] = 1.f/(1.f+expf(-sa));
        c_gate_v[t] = 1.f/(1.f+expf(-sv));
    } else if (t == 16) {
        float s = bt[0];
        #pragma unroll
        for (int c = 0; c < CC; c++) s += cfs[c]*Wt[c];
        float sp = (s > 20.f) ? s : log1pf(expf(s));
        c_misc[0] = sp + 1.0f;
    } else if (t == 17) {
        float s = 0.f;
        #pragma unroll
        for (int c = 0; c < CC; c++) s += cfs[c];
        s *= (1.0f/CC);
        c_misc[1] = (1.f/(1.f+expf(-s)))*0.5f + 0.5f;
    }

    float vals[4];
    float s1 = 0.f, s2 = 0.f;
    #pragma unroll
    for (int l = 0; l < 4; l++) {
        int i = t*4 + l;
        float a = b1[i];
        #pragma unroll
        for (int c = 0; c < CC; c++) a += cfs[c]*W1[i*CC+c];
        vals[l] = a; s1 += a; s2 += a*a;
    }
    red[t] = s1; red2[t] = s2; __syncthreads();
    for (int o = 128; o > 0; o >>= 1) {
        if (t < o) { red[t] += red[t+o]; red2[t] += red2[t+o]; }
        __syncthreads();
    }
    float m = red[0]*(1.0f/DD);
    float var = red2[0]*(1.0f/DD) - m*m;
    float inv = rsqrtf(var + 1e-5f);
    #pragma unroll
    for (int l = 0; l < 4; l++) {
        int i = t*4 + l;
        float h = (vals[l]-m)*inv*g1[i] + bb1[i];
        c_h1[i] = fmaxf(h, 0.f);
    }
}

__global__ void chaos2_kernel(const float* __restrict__ W2, const float* __restrict__ b2) {
    __shared__ float h1s[DD];
    __shared__ float red[256];
    int t = threadIdx.x;
    #pragma unroll
    for (int l = 0; l < 4; l++) h1s[t + l*256] = c_h1[t + l*256];
    __syncthreads();
    int r = t >> 4, c = t & 15;
    int i = blockIdx.x*16 + r;
    float s = 0.f;
    for (int j = c; j < DD; j += 16) s += h1s[j]*W2[(size_t)i*DD + j];
    red[t] = s; __syncthreads();
    for (int o = 8; o > 0; o >>= 1) {
        if (c < o) red[t] += red[t+o];
        __syncthreads();
    }
    if (c == 0) c_cepre[i] = red[r*16] + b2[i];
}

__global__ void chaos3_kernel(const float* __restrict__ g2, const float* __restrict__ bb2,
                              const float* __restrict__ qrot, const float* __restrict__ fscales) {
    __shared__ float ce[DD];
    __shared__ float scs[DD];
    __shared__ float red[256], red2[256];
    int t = threadIdx.x;
    float vals[4]; float s1 = 0.f, s2 = 0.f;
    #pragma unroll
    for (int l = 0; l < 4; l++) {
        int i = t + l*256;
        vals[l] = c_cepre[i]; s1 += vals[l]; s2 += vals[l]*vals[l];
    }
    red[t] = s1; red2[t] = s2; __syncthreads();
    for (int o = 128; o > 0; o >>= 1) {
        if (t < o) { red[t] += red[t+o]; red2[t] += red2[t+o]; }
        __syncthreads();
    }
    float m = red[0]*(1.0f/DD);
    float var = red2[0]*(1.0f/DD) - m*m;
    float inv = rsqrtf(var + 1e-5f);
    #pragma unroll
    for (int l = 0; l < 4; l++) {
        int i = t + l*256;
        ce[i] = (vals[l]-m)*inv*g2[i] + bb2[i];
    }
    __syncthreads();
    float sfs = 1.f/(1.f+expf(-fscales[0]));
    #pragma unroll
    for (int l = 0; l < 4; l++) {
        int i = t + l*256;
        int h = i >> 6, d = i & 63;
        float s = 0.f;
        #pragma unroll 8
        for (int e = 0; e < HD; e++) s += ce[h*HD+e]*qrot[e*HD+d];
        s *= sfs;
        scs[i] = s;
        c_vadd[i] = s * c_gate_v[h];
    }
    __syncthreads();
    if (t < HH) {
        float bsum = 0.f;
        for (int d = 0; d < HD; d++) bsum += scs[t*HD + d];
        float temp = c_misc[0];
        c_alpha[t] = c_gate_a[t]/(8.f*temp);
        c_beta[t]  = bsum/temp;
    }
}

// ---------------- LN-pre ----------------
__global__ void ln_pre_kernel(const float* __restrict__ x,
                              const float* __restrict__ g, const float* __restrict__ b) {
    __shared__ float red[256], red2[256];
    size_t row = blockIdx.x;
    const float* xr = x + row*DD;
    float* o = g_xn + row*DD;
    int t = threadIdx.x;
    float vals[4]; float s1 = 0.f, s2 = 0.f;
    #pragma unroll
    for (int l = 0; l < 4; l++) {
        vals[l] = xr[t + l*256]; s1 += vals[l]; s2 += vals[l]*vals[l];
    }
    red[t] = s1; red2[t] = s2; __syncthreads();
    for (int off = 128; off > 0; off >>= 1) {
        if (t < off) { red[t] += red[t+off]; red2[t] += red2[t+off]; }
        __syncthreads();
    }
    float m = red[0]*(1.0f/DD);
    float var = red2[0]*(1.0f/DD) - m*m;
    float inv = rsqrtf(var + 1e-5f);
    #pragma unroll
    for (int l = 0; l < 4; l++) {
        int i = t + l*256;
        o[i] = (vals[l]-m)*inv*g[i] + b[i];
    }
}

// ============================================================================
// tf32 tensor-core GEMM for QKV / out-proj (NT): C = A[M,K] x B[N,K]^T
// ============================================================================
struct EpiQKV {
    const float* bias;
    __device__ __forceinline__ void init(int) {}
    __device__ __forceinline__ void write(int m, int n, float v) const {
        float val = v + bias[n];
        int b = m >> 11, s = m & 2047;
        int which = n >> 10, rest = n & 1023;
        size_t dst = (((size_t)(b*HH + (rest >> 6)))*SS + s)*HD + (rest & 63);
        if (which == 0)      g_q[dst] = to_tf32(val);
        else if (which == 1) g_k[dst] = to_tf32(val);
        else                 g_v[dst] = to_tf32(val + c_vadd[rest]);
    }
};

struct EpiOut {
    const float* bias;
    __device__ __forceinline__ void init(int) {}
    __device__ __forceinline__ void write(int m, int n, float v) const {
        g_proj[(size_t)m*DD + n] = v + bias[n];
    }
};

template<int BN, int WN, typename Epi>
__global__ __launch_bounds__(256, 2) void mma_gemm(
    const float* __restrict__ A, int lda,
    const float* __restrict__ B, int ldb,
    int K, Epi epi)
{
    constexpr int BM = 128, BK = 32;
    constexpr int NI = WN / 8;
    __shared__ float As[BM*BK];
    __shared__ float Bs[BN*BK];

    int t = threadIdx.x;
    int lane = t & 31, warp = t >> 5;
    int q = lane >> 2, r = lane & 3;
    int wm = (warp >> 1) * 32;
    int wn = (warp & 1) * WN;
    int m0 = blockIdx.y * BM, n0 = blockIdx.x * BN;
    epi.init(0);

    float acc[2][NI][4];
    #pragma unroll
    for (int mi = 0; mi < 2; mi++)
        #pragma unroll
        for (int nj = 0; nj < NI; nj++)
            #pragma unroll
            for (int p = 0; p < 4; p++) acc[mi][nj][p] = 0.f;

    for (int k0 = 0; k0 < K; k0 += BK) {
        #pragma unroll
        for (int i = 0; i < BM*BK/1024; i++) {
            int f = t + i*256;
            int row = f >> 3, k4 = f & 7;
            float4 v = *(const float4*)(A + (size_t)(m0+row)*lda + k0 + k4*4);
            v.x = to_tf32(v.x); v.y = to_tf32(v.y); v.z = to_tf32(v.z); v.w = to_tf32(v.w);
            *(float4*)&As[row*32 + ((k4 ^ (row & 7)) << 2)] = v;
        }
        #pragma unroll
        for (int i = 0; i < BN*BK/1024; i++) {
            int f = t + i*256;
            int row = f >> 3, k4 = f & 7;
            float4 v = *(const float4*)(B + (size_t)(n0+row)*ldb + k0 + k4*4);
            v.x = to_tf32(v.x); v.y = to_tf32(v.y); v.z = to_tf32(v.z); v.w = to_tf32(v.w);
            *(float4*)&Bs[row*32 + ((k4 ^ (row & 7)) << 2)] = v;
        }
        __syncthreads();

        #pragma unroll
        for (int ks = 0; ks < 4; ks++) {
            uint32_t af[2][4];
            #pragma unroll
            for (int mi = 0; mi < 2; mi++) {
                #pragma unroll
                for (int p = 0; p < 4; p++) {
                    int row = wm + mi*16 + q + ((p & 1) << 3);
                    int kk  = ks*8 + r + ((p >> 1) << 2);
                    af[mi][p] = __float_as_uint(
                        As[row*32 + (((kk >> 2) ^ (row & 7)) << 2) + (kk & 3)]);
                }
            }
            uint32_t bf[NI][2];
            #pragma unroll
            for (int nj = 0; nj < NI; nj++) {
                int col = wn + nj*8 + q;
                #pragma unroll
                for (int p = 0; p < 2; p++) {
                    int kk = ks*8 + r + p*4;
                    bf[nj][p] = __float_as_uint(
                        Bs[col*32 + (((kk >> 2) ^ (col & 7)) << 2) + (kk & 3)]);
                }
            }
            #pragma unroll
            for (int mi = 0; mi < 2; mi++)
                #pragma unroll
                for (int nj = 0; nj < NI; nj++)
                    mma_tf32(acc[mi][nj], af[mi], bf[nj][0], bf[nj][1]);
        }
        __syncthreads();
    }

    #pragma unroll
    for (int mi = 0; mi < 2; mi++)
        #pragma unroll
        for (int nj = 0; nj < NI; nj++)
            #pragma unroll
            for (int p = 0; p < 4; p++) {
                int m = m0 + wm + mi*16 + q + ((p >> 1) << 3);
                int n = n0 + wn + nj*8 + 2*r + (p & 1);
                epi.write(m, n, acc[mi][nj][p]);
            }
}

// ============================================================================
// Fused attention: scores + exp + rowsum + PV in pass 1, w write in pass 2.
// grid (16 m-tiles, 32 bh), 256 threads = 8 warps (4 row-groups x 2 col-halves)
// Warp tile: 32 rows x 64 keys. No max subtraction (|s| < ~3).
// ============================================================================
#define QS_STRIDE 68
#define VS_STRIDE 72
#define QS_FLOATS (128*QS_STRIDE)   // 8704
#define VS_FLOATS (128*VS_STRIDE)   // 9216
#define ATT_SMEM_FLOATS (3*QS_FLOATS + 2*VS_FLOATS)  // 44544
#define ATT_SMEM_BYTES (ATT_SMEM_FLOATS*4)           // 178176

__device__ __forceinline__ void load_tile_async(float* dst, const float* src,
                                                int stride, int t) {
    #pragma unroll
    for (int i = 0; i < 8; i++) {
        int f = t + i*256;
        int row = f >> 4, k4 = f & 15;
        cp16(dst + row*stride + k4*4, src + row*HD + k4*4);
    }
}

__global__ void __launch_bounds__(256, 1) attn_fused(
    const float* __restrict__ qg, const float* __restrict__ kg,
    const float* __restrict__ vg, float* __restrict__ wout)
{
    extern __shared__ float sm[];
    float* qs  = sm;
    float* ks0 = sm + QS_FLOATS;
    float* ks1 = sm + 2*QS_FLOATS;
    float* vs0 = sm + 3*QS_FLOATS;
    float* vs1 = sm + 3*QS_FLOATS + VS_FLOATS;
    __shared__ float l_part[2][128];

    int t = threadIdx.x, lane = t & 31, warp = t >> 5;
    int q = lane >> 2, r = lane & 3;
    int wr = warp >> 1, wc = warp & 1;
    int mtile = blockIdx.x, bh = blockIdx.y;
    int m0 = mtile*128;
    int h = bh & 15, b = bh >> 4;
    const float* Q = qg + ((size_t)bh*SS + m0)*HD;
    const float* K = kg + (size_t)bh*SS*HD;
    const float* V = vg + (size_t)bh*SS*HD;
    float al = c_alpha[h], be = c_beta[h];

    // load Q tile (persistent)
    #pragma unroll
    for (int i = 0; i < 8; i++) {
        int f = t + i*256;
        int row = f >> 4, k4 = f & 15;
        *(float4*)(qs + row*QS_STRIDE + k4*4) = *(const float4*)(Q + row*HD + k4*4);
    }

    float O[2][8][4] = {};
    float rs[2][2] = {};

    // prefetch tile 0
    load_tile_async(ks0, K, QS_STRIDE, t);
    load_tile_async(vs0, V, VS_STRIDE, t);
    cp_commit();

    int src0 = (lane & ~3) | (r >> 1);
    int src1 = src0 + 2;
    bool odd = (r & 1);

    // ---------------- pass 1 ----------------
    for (int kt = 0; kt < 16; kt++) {
        float* kss = (kt & 1) ? ks1 : ks0;
        float* vss = (kt & 1) ? vs1 : vs0;
        if (kt < 15) {
            float* kn = (kt & 1) ? ks0 : ks1;
            float* vn = (kt & 1) ? vs0 : vs1;
            load_tile_async(kn, K + (size_t)(kt+1)*128*HD, QS_STRIDE, t);
            load_tile_async(vn, V + (size_t)(kt+1)*128*HD, VS_STRIDE, t);
            cp_commit();
            cp_wait1();
        } else {
            cp_wait0();
        }
        __syncthreads();

        #pragma unroll
        for (int hh = 0; hh < 2; hh++) {
            int colb = wc*64 + hh*32;
            float acc[2][4][4] = {};
            // ---- QK^T over K=64 ----
            #pragma unroll
            for (int ks2 = 0; ks2 < 8; ks2++) {
                uint32_t af[2][4];
                #pragma unroll
                for (int mi = 0; mi < 2; mi++) {
                    int row = wr*32 + mi*16 + q;
                    af[mi][0] = __float_as_uint(qs[row*QS_STRIDE + ks2*8 + r]);
                    af[mi][1] = __float_as_uint(qs[(row+8)*QS_STRIDE + ks2*8 + r]);
                    af[mi][2] = __float_as_uint(qs[row*QS_STRIDE + ks2*8 + r + 4]);
                    af[mi][3] = __float_as_uint(qs[(row+8)*QS_STRIDE + ks2*8 + r + 4]);
                }
                #pragma unroll
                for (int g = 0; g < 4; g++) {
                    int col = colb + g*8 + q;
                    uint32_t b0 = __float_as_uint(kss[col*QS_STRIDE + ks2*8 + r]);
                    uint32_t b1 = __float_as_uint(kss[col*QS_STRIDE + ks2*8 + r + 4]);
                    mma_tf32(acc[0][g], af[0], b0, b1);
                    mma_tf32(acc[1][g], af[1], b0, b1);
                }
            }
            // ---- exp + row sums ----
            #pragma unroll
            for (int mi = 0; mi < 2; mi++)
                #pragma unroll
                for (int g = 0; g < 4; g++) {
                    float e0 = fast_exp(fmaf(al, acc[mi][g][0], be));
                    float e1 = fast_exp(fmaf(al, acc[mi][g][1], be));
                    float e2 = fast_exp(fmaf(al, acc[mi][g][2], be));
                    float e3 = fast_exp(fmaf(al, acc[mi][g][3], be));
                    acc[mi][g][0] = e0; acc[mi][g][1] = e1;
                    acc[mi][g][2] = e2; acc[mi][g][3] = e3;
                    rs[mi][0] += e0 + e1;
                    rs[mi][1] += e2 + e3;
                }
            // ---- PV: O += expS @ V ----
            #pragma unroll
            for (int g = 0; g < 4; g++) {
                int kb = colb + g*8;
                uint32_t bf[8][2];
                #pragma unroll
                for (int nj = 0; nj < 8; nj++) {
                    bf[nj][0] = __float_as_uint(vss[(kb + r)*VS_STRIDE + nj*8 + q]);
                    bf[nj][1] = __float_as_uint(vss[(kb + r + 4)*VS_STRIDE + nj*8 + q]);
                }
                #pragma unroll
                for (int mi = 0; mi < 2; mi++) {
                    float e0 = __shfl_sync(0xffffffffu, acc[mi][g][0], src0);
                    float o0 = __shfl_sync(0xffffffffu, acc[mi][g][1], src0);
                    float e1 = __shfl_sync(0xffffffffu, acc[mi][g][2], src0);
                    float o1 = __shfl_sync(0xffffffffu, acc[mi][g][3], src0);
                    float e2 = __shfl_sync(0xffffffffu, acc[mi][g][0], src1);
                    float o2 = __shfl_sync(0xffffffffu, acc[mi][g][1], src1);
                    float e3 = __shfl_sync(0xffffffffu, acc[mi][g][2], src1);
                    float o3 = __shfl_sync(0xffffffffu, acc[mi][g][3], src1);
                    uint32_t af[4];
                    af[0] = __float_as_uint(to_tf32(odd ? o0 : e0));
                    af[1] = __float_as_uint(to_tf32(odd ? o1 : e1));
                    af[2] = __float_as_uint(to_tf32(odd ? o2 : e2));
                    af[3] = __float_as_uint(to_tf32(odd ? o3 : e3));
                    #pragma unroll
                    for (int nj = 0; nj < 8; nj++)
                        mma_tf32(O[mi][nj], af, bf[nj][0], bf[nj][1]);
                }
            }
        }
        __syncthreads();
    }

    // ---------------- row-sum reduction ----------------
    #pragma unroll
    for (int mi = 0; mi < 2; mi++)
        #pragma unroll
        for (int j = 0; j < 2; j++) {
            rs[mi][j] += __shfl_xor_sync(0xffffffffu, rs[mi][j], 1);
            rs[mi][j] += __shfl_xor_sync(0xffffffffu, rs[mi][j], 2);
        }
    if (r == 0) {
        #pragma unroll
        for (int mi = 0; mi < 2; mi++)
            #pragma unroll
            for (int j = 0; j < 2; j++)
                l_part[wc][wr*32 + mi*16 + j*8 + q] = rs[mi][j];
    }
    __syncthreads();
    float inv[2][2];
    #pragma unroll
    for (int mi = 0; mi < 2; mi++)
        #pragma unroll
        for (int j = 0; j < 2; j++) {
            int row = wr*32 + mi*16 + j*8 + q;
            inv[mi][j] = 1.0f / (l_part[0][row] + l_part[1][row]);
        }

    // ---------------- O pair reduction + store ----------------
    float* scr = vs0;  // reuse (8192 floats needed)
    if (wc == 1) {
        #pragma unroll
        for (int mi = 0; mi < 2; mi++)
            #pragma unroll
            for (int nj = 0; nj < 8; nj++)
                #pragma unroll
                for (int p = 0; p < 4; p++) {
                    int idx = (mi*8 + nj)*4 + p;
                    scr[(wr*64 + idx)*32 + lane] = O[mi][nj][p];
                }
    }
    __syncthreads();
    if (wc == 0) {
        #pragma unroll
        for (int mi = 0; mi < 2; mi++)
            #pragma unroll
            for (int nj = 0; nj < 8; nj++) {
                #pragma unroll
                for (int p = 0; p < 4; p++) {
                    int idx = (mi*8 + nj)*4 + p;
                    O[mi][nj][p] += scr[(wr*64 + idx)*32 + lane];
                }
                int row = m0 + wr*32 + mi*16 + q;
                int col = h*64 + nj*8 + 2*r;
                float2 v0 = make_float2(O[mi][nj][0]*inv[mi][0], O[mi][nj][1]*inv[mi][0]);
                float2 v1 = make_float2(O[mi][nj][2]*inv[mi][1], O[mi][nj][3]*inv[mi][1]);
                *(float2*)&g_att[((size_t)(b*SS + row))*DD + col] = v0;
                *(float2*)&g_att[((size_t)(b*SS + row + 8))*DD + col] = v1;
            }
    }
    __syncthreads();

    // ---------------- pass 2: recompute S, write normalized w ----------------
    float* wbh = wout + (size_t)bh*SS*SS;
    load_tile_async(ks0, K, QS_STRIDE, t);
    cp_commit();
    for (int kt = 0; kt < 16; kt++) {
        float* kss = (kt & 1) ? ks1 : ks0;
        if (kt < 15) {
            float* kn = (kt & 1) ? ks0 : ks1;
            load_tile_async(kn, K + (size_t)(kt+1)*128*HD, QS_STRIDE, t);
            cp_commit();
            cp_wait1();
        } else {
            cp_wait0();
        }
        __syncthreads();

        #pragma unroll
        for (int hh = 0; hh < 2; hh++) {
            int colb = wc*64 + hh*32;
            float acc[2][4][4] = {};
            #pragma unroll
            for (int ks2 = 0; ks2 < 8; ks2++) {
                uint32_t af[2][4];
                #pragma unroll
                for (int mi = 0; mi < 2; mi++) {
                    int row = wr*32 + mi*16 + q;
                    af[mi][0] = __float_as_uint(qs[row*QS_STRIDE + ks2*8 + r]);
                    af[mi][1] = __float_as_uint(qs[(row+8)*QS_STRIDE + ks2*8 + r]);
                    af[mi][2] = __float_as_uint(qs[row*QS_STRIDE + ks2*8 + r + 4]);
                    af[mi][3] = __float_as_uint(qs[(row+8)*QS_STRIDE + ks2*8 + r + 4]);
                }
                #pragma unroll
                for (int g = 0; g < 4; g++) {
                    int col = colb + g*8 + q;
                    uint32_t b0 = __float_as_uint(kss[col*QS_STRIDE + ks2*8 + r]);
                    uint32_t b1 = __float_as_uint(kss[col*QS_STRIDE + ks2*8 + r + 4]);
                    mma_tf32(acc[0][g], af[0], b0, b1);
                    mma_tf32(acc[1][g], af[1], b0, b1);
                }
            }
            #pragma unroll
            for (int mi = 0; mi < 2; mi++) {
                int row = m0 + wr*32 + mi*16 + q;
                #pragma unroll
                for (int g = 0; g < 4; g++) {
                    int col = kt*128 + colb + g*8 + 2*r;
                    float e0 = fast_exp(fmaf(al, acc[mi][g][0], be)) * inv[mi][0];
                    float e1 = fast_exp(fmaf(al, acc[mi][g][1], be)) * inv[mi][0];
                    float e2 = fast_exp(fmaf(al, acc[mi][g][2], be)) * inv[mi][1];
                    float e3 = fast_exp(fmaf(al, acc[mi][g][3], be)) * inv[mi][1];
                    __stcs((float2*)&wbh[(size_t)row*SS + col], make_float2(e0, e1));
                    __stcs((float2*)&wbh[(size_t)(row+8)*SS + col], make_float2(e2, e3));
                }
            }
        }
        __syncthreads();
    }
}

// ---------------- final: mix + LN-post ----------------
__global__ void final_kernel(const float* __restrict__ g, const float* __restrict__ b,
                             float* __restrict__ out) {
    __shared__ float red[256], red2[256];
    size_t row = blockIdx.x;
    int t = threadIdx.x;
    float gm = c_misc[1];
    float vals[4]; float s1 = 0.f, s2 = 0.f;
    #pragma unroll
    for (int l = 0; l < 4; l++) {
        size_t idx = row*DD + t + l*256;
        float vv = g_proj[idx]*gm + g_xn[idx]*(1.f - gm);
        vals[l] = vv; s1 += vv; s2 += vv*vv;
    }
    red[t] = s1; red2[t] = s2; __syncthreads();
    for (int off = 128; off > 0; off >>= 1) {
        if (t < off) { red[t] += red[t+off]; red2[t] += red2[t+off]; }
        __syncthreads();
    }
    float m = red[0]*(1.0f/DD);
    float var = red2[0]*(1.0f/DD) - m*m;
    float inv = rsqrtf(var + 1e-5f);
    #pragma unroll
    for (int l = 0; l < 4; l++) {
        int i = t + l*256;
        out[row*DD + i] = (vals[l]-m)*inv*g[i] + b[i];
    }
}

// ---------------------------------------------------------------------------
extern "C" void kernel_launch(void* const* d_in, const int* in_sizes, int n_in,
                              void* d_out, int out_size) {
    const float* x      = (const float*)d_in[0];
    const float* cf     = (const float*)d_in[1];
    const float* lnpg   = (const float*)d_in[2];
    const float* lnpb   = (const float*)d_in[3];
    const float* Wqkv   = (const float*)d_in[4];
    const float* bqkv   = (const float*)d_in[5];
    const float* eW1    = (const float*)d_in[6];
    const float* eb1    = (const float*)d_in[7];
    const float* eg1    = (const float*)d_in[8];
    const float* ebb1   = (const float*)d_in[9];
    const float* eW2    = (const float*)d_in[10];
    const float* eb2    = (const float*)d_in[11];
    const float* eg2    = (const float*)d_in[12];
    const float* ebb2   = (const float*)d_in[13];
    const float* Wga    = (const float*)d_in[14];
    const float* bga    = (const float*)d_in[15];
    const float* Wgv    = (const float*)d_in[16];
    const float* bgv    = (const float*)d_in[17];
    const float* Wt     = (const float*)d_in[18];
    const float* bt     = (const float*)d_in[19];
    const float* qrot   = (const float*)d_in[20];
    const float* fsc    = (const float*)d_in[21];
    const float* Wout   = (const float*)d_in[22];
    const float* bout   = (const float*)d_in[23];
    const float* lnqg   = (const float*)d_in[24];
    const float* lnqb   = (const float*)d_in[25];

    float* out = (float*)d_out;

    size_t need = (size_t)BS*DD + (size_t)BH*SS*SS;
    float* wbuf;
    if ((size_t)out_size >= need) {
        wbuf = out + (size_t)BS*DD;
    } else {
        float* wptr = nullptr;
        cudaGetSymbolAddress((void**)&wptr, g_w);
        wbuf = wptr;
    }

    float *xn_p, *q_p, *k_p, *v_p, *att_p;
    cudaGetSymbolAddress((void**)&xn_p,  g_xn);
    cudaGetSymbolAddress((void**)&q_p,   g_q);
    cudaGetSymbolAddress((void**)&k_p,   g_k);
    cudaGetSymbolAddress((void**)&v_p,   g_v);
    cudaGetSymbolAddress((void**)&att_p, g_att);

    static bool attr_set = false;
    if (!attr_set) {
        cudaFuncSetAttribute(attn_fused,
                             cudaFuncAttributeMaxDynamicSharedMemorySize,
                             ATT_SMEM_BYTES);
        attr_set = true;
    }

    chaos1_kernel<<<1, 256>>>(cf, eW1, eb1, eg1, ebb1, Wga, bga, Wgv, bgv, Wt, bt);
    chaos2_kernel<<<64, 256>>>(eW2, eb2);
    chaos3_kernel<<<1, 256>>>(eg2, ebb2, qrot, fsc);

    ln_pre_kernel<<<BS, 256>>>(x, lnpg, lnpb);

    // QKV: C[4096,3072] = xn @ Wqkv^T
    mma_gemm<128, 64><<<dim3(3*DD/128, BS/128), 256>>>(
        xn_p, DD, Wqkv, DD, DD, EpiQKV{bqkv});

    // fused attention (scores+softmax+PV+w-write)
    attn_fused<<<dim3(SS/128, BH), 256, ATT_SMEM_BYTES>>>(q_p, k_p, v_p, wbuf);

    // out projection: C[4096,1024] = att @ Wout^T
    mma_gemm<128, 64><<<dim3(DD/128, BS/128), 256>>>(
        att_p, DD, Wout, DD, DD, EpiOut{bout});

    final_kernel<<<BS, 256>>>(lnqg, lnqb, out);
}

// round 5
// speedup vs baseline: 6.4898x; 1.6736x over previous
#include <cuda_runtime.h>
#include <cuda_fp16.h>
#include <math.h>
#include <stdint.h>

#define BB 2
#define SS 2048
#define DD 1024
#define HH 16
#define HD 64
#define CC 16
#define BS (BB*SS)
#define BH (BB*HH)

// ---------------- device scratch ----------------
__device__ __align__(256) float  g_xn[BS*DD];           // fp32 LN(x) for final mix
__device__ __align__(256) __half g_xnh[BS*DD];          // half LN(x) for GEMM
__device__ __align__(256) __half g_qh[BH*SS*HD];
__device__ __align__(256) __half g_kh[BH*SS*HD];
__device__ __align__(256) __half g_vth[BH*HD*SS];       // V transposed: [bh][hd][s]
__device__ __align__(256) __half g_atth[BS*DD];
__device__ __align__(256) float  g_proj[BS*DD];
__device__ __align__(256) __half g_wqkvh[3*DD*DD];
__device__ __align__(256) __half g_wouth[DD*DD];
__device__ __align__(256) float  g_w[(size_t)BH*SS*SS]; // fallback w buffer

__device__ float c_h1[DD];
__device__ float c_cepre[DD];
__device__ float c_gate_a[HH];
__device__ float c_gate_v[HH];
__device__ float c_misc[2];
__device__ float c_alpha[HH];
__device__ float c_beta[HH];
__device__ float c_vadd[DD];

// ---------------- helpers ----------------
__device__ __forceinline__ uint32_t pack_h2(float a, float b) {
    __half2 h = __floats2half2_rn(a, b);
    return *reinterpret_cast<uint32_t*>(&h);
}

// fast 2^x, degree-4 (rel err ~4e-5 on f in [-0.5,0.5])
__device__ __forceinline__ float fast_exp2(float x) {
    float z = x + 12582912.0f;
    int   i = __float_as_int(z);
    float f = x - (z - 12582912.0f);
    float p = 9.618129e-3f;
    p = fmaf(p, f, 5.5504109e-2f);
    p = fmaf(p, f, 2.4022651e-1f);
    p = fmaf(p, f, 6.9314718e-1f);
    p = fmaf(p, f, 1.0f);
    return __int_as_float(__float_as_int(p) + (i << 23));
}

__device__ __forceinline__ void mma_f16(float c[4], const uint32_t a[4],
                                        uint32_t b0, uint32_t b1) {
    asm volatile(
        "mma.sync.aligned.m16n8k16.row.col.f32.f16.f16.f32 "
        "{%0,%1,%2,%3}, {%4,%5,%6,%7}, {%8,%9}, {%0,%1,%2,%3};"
        : "+f"(c[0]), "+f"(c[1]), "+f"(c[2]), "+f"(c[3])
        : "r"(a[0]), "r"(a[1]), "r"(a[2]), "r"(a[3]), "r"(b0), "r"(b1));
}

__device__ __forceinline__ void cp16h(__half* dst, const __half* src) {
    unsigned d = (unsigned)__cvta_generic_to_shared(dst);
    asm volatile("cp.async.cg.shared.global [%0], [%1], 16;" :: "r"(d), "l"(src));
}
__device__ __forceinline__ void cp_commit() { asm volatile("cp.async.commit_group;"); }
__device__ __forceinline__ void cp_wait1() { asm volatile("cp.async.wait_group 1;"); }
__device__ __forceinline__ void cp_wait0() { asm volatile("cp.async.wait_group 0;"); }

// ---------------- chaos encoder ----------------
__global__ void chaos1_kernel(const float* __restrict__ cf,
                              const float* __restrict__ W1, const float* __restrict__ b1,
                              const float* __restrict__ g1, const float* __restrict__ bb1,
                              const float* __restrict__ Wga, const float* __restrict__ bga,
                              const float* __restrict__ Wgv, const float* __restrict__ bgv,
                              const float* __restrict__ Wt,  const float* __restrict__ bt) {
    __shared__ float cfs[CC];
    __shared__ float red[256], red2[256];
    int t = threadIdx.x;
    if (t < CC) cfs[t] = cf[t];
    __syncthreads();

    if (t < HH) {
        float sa = bga[t], sv = bgv[t];
        #pragma unroll
        for (int c = 0; c < CC; c++) { sa += cfs[c]*Wga[t*CC+c]; sv += cfs[c]*Wgv[t*CC+c]; }
        c_gate_a[t] = 1.f/(1.f+expf(-sa));
        c_gate_v[t] = 1.f/(1.f+expf(-sv));
    } else if (t == 16) {
        float s = bt[0];
        #pragma unroll
        for (int c = 0; c < CC; c++) s += cfs[c]*Wt[c];
        float sp = (s > 20.f) ? s : log1pf(expf(s));
        c_misc[0] = sp + 1.0f;
    } else if (t == 17) {
        float s = 0.f;
        #pragma unroll
        for (int c = 0; c < CC; c++) s += cfs[c];
        s *= (1.0f/CC);
        c_misc[1] = (1.f/(1.f+expf(-s)))*0.5f + 0.5f;
    }

    float vals[4];
    float s1 = 0.f, s2 = 0.f;
    #pragma unroll
    for (int l = 0; l < 4; l++) {
        int i = t*4 + l;
        float a = b1[i];
        #pragma unroll
        for (int c = 0; c < CC; c++) a += cfs[c]*W1[i*CC+c];
        vals[l] = a; s1 += a; s2 += a*a;
    }
    red[t] = s1; red2[t] = s2; __syncthreads();
    for (int o = 128; o > 0; o >>= 1) {
        if (t < o) { red[t] += red[t+o]; red2[t] += red2[t+o]; }
        __syncthreads();
    }
    float m = red[0]*(1.0f/DD);
    float var = red2[0]*(1.0f/DD) - m*m;
    float inv = rsqrtf(var + 1e-5f);
    #pragma unroll
    for (int l = 0; l < 4; l++) {
        int i = t*4 + l;
        float h = (vals[l]-m)*inv*g1[i] + bb1[i];
        c_h1[i] = fmaxf(h, 0.f);
    }
}

__global__ void chaos2_kernel(const float* __restrict__ W2, const float* __restrict__ b2) {
    __shared__ float h1s[DD];
    __shared__ float red[256];
    int t = threadIdx.x;
    #pragma unroll
    for (int l = 0; l < 4; l++) h1s[t + l*256] = c_h1[t + l*256];
    __syncthreads();
    int r = t >> 4, c = t & 15;
    int i = blockIdx.x*16 + r;
    float s = 0.f;
    for (int j = c; j < DD; j += 16) s += h1s[j]*W2[(size_t)i*DD + j];
    red[t] = s; __syncthreads();
    for (int o = 8; o > 0; o >>= 1) {
        if (c < o) red[t] += red[t+o];
        __syncthreads();
    }
    if (c == 0) c_cepre[i] = red[r*16] + b2[i];
}

__global__ void chaos3_kernel(const float* __restrict__ g2, const float* __restrict__ bb2,
                              const float* __restrict__ qrot, const float* __restrict__ fscales) {
    __shared__ float ce[DD];
    __shared__ float scs[DD];
    __shared__ float red[256], red2[256];
    int t = threadIdx.x;
    float vals[4]; float s1 = 0.f, s2 = 0.f;
    #pragma unroll
    for (int l = 0; l < 4; l++) {
        int i = t + l*256;
        vals[l] = c_cepre[i]; s1 += vals[l]; s2 += vals[l]*vals[l];
    }
    red[t] = s1; red2[t] = s2; __syncthreads();
    for (int o = 128; o > 0; o >>= 1) {
        if (t < o) { red[t] += red[t+o]; red2[t] += red2[t+o]; }
        __syncthreads();
    }
    float m = red[0]*(1.0f/DD);
    float var = red2[0]*(1.0f/DD) - m*m;
    float inv = rsqrtf(var + 1e-5f);
    #pragma unroll
    for (int l = 0; l < 4; l++) {
        int i = t + l*256;
        ce[i] = (vals[l]-m)*inv*g2[i] + bb2[i];
    }
    __syncthreads();
    float sfs = 1.f/(1.f+expf(-fscales[0]));
    #pragma unroll
    for (int l = 0; l < 4; l++) {
        int i = t + l*256;
        int h = i >> 6, d = i & 63;
        float s = 0.f;
        #pragma unroll 8
        for (int e = 0; e < HD; e++) s += ce[h*HD+e]*qrot[e*HD+d];
        s *= sfs;
        scs[i] = s;
        c_vadd[i] = s * c_gate_v[h];
    }
    __syncthreads();
    if (t < HH) {
        float bsum = 0.f;
        for (int d = 0; d < HD; d++) bsum += scs[t*HD + d];
        float temp = c_misc[0];
        c_alpha[t] = c_gate_a[t]/(8.f*temp);
        c_beta[t]  = bsum/temp;
    }
}

// ---------------- LN-pre: writes fp32 + half ----------------
__global__ void ln_pre_kernel(const float* __restrict__ x,
                              const float* __restrict__ g, const float* __restrict__ b) {
    __shared__ float red[256], red2[256];
    size_t row = blockIdx.x;
    const float4* xr = (const float4*)(x + row*DD);
    int t = threadIdx.x;
    float4 v = xr[t];
    float s1 = v.x + v.y + v.z + v.w;
    float s2 = v.x*v.x + v.y*v.y + v.z*v.z + v.w*v.w;
    red[t] = s1; red2[t] = s2; __syncthreads();
    for (int off = 128; off > 0; off >>= 1) {
        if (t < off) { red[t] += red[t+off]; red2[t] += red2[t+off]; }
        __syncthreads();
    }
    float m = red[0]*(1.0f/DD);
    float var = red2[0]*(1.0f/DD) - m*m;
    float inv = rsqrtf(var + 1e-5f);
    int i = t*4;
    float4 gg = *(const float4*)(g + i);
    float4 bb = *(const float4*)(b + i);
    float4 o;
    o.x = (v.x-m)*inv*gg.x + bb.x;
    o.y = (v.y-m)*inv*gg.y + bb.y;
    o.z = (v.z-m)*inv*gg.z + bb.z;
    o.w = (v.w-m)*inv*gg.w + bb.w;
    *(float4*)(g_xn + row*DD + i) = o;
    uint2 h;
    h.x = pack_h2(o.x, o.y);
    h.y = pack_h2(o.z, o.w);
    *(uint2*)(g_xnh + row*DD + i) = h;
}

// ---------------- convert weights to half ----------------
__global__ void round_weights(const float* __restrict__ Wqkv,
                              const float* __restrict__ Wout) {
    size_t i = (size_t)blockIdx.x*256 + threadIdx.x;      // float4 index
    const size_t nqkv = (size_t)3*DD*DD/4;
    float4 v;
    __half* dst;
    if (i < nqkv) {
        v = ((const float4*)Wqkv)[i];
        dst = g_wqkvh + i*4;
    } else {
        v = ((const float4*)Wout)[i - nqkv];
        dst = g_wouth + (i - nqkv)*4;
    }
    uint2 h;
    h.x = pack_h2(v.x, v.y);
    h.y = pack_h2(v.z, v.w);
    *(uint2*)dst = h;
}

// ============================================================================
// fp16 tensor-core GEMM (NT): C[M,N] = A[M,K] x B[N,K]^T, fp32 accum.
// BM=128, BN=128, BK=64; 256 threads, warps 4x2 (warp tile 32x64).
// cp.async double-buffered; padded smem stride 72 halves (conflict-free).
// ============================================================================
#define GE_BK 64
#define GE_STR 72
#define GE_TILE_H (128*GE_STR)            // halves per tile
#define GE_SMEM_BYTES (4*GE_TILE_H*2)     // A0,B0,A1,B1 = 73728

struct EpiQKV {
    const float* bias;
    __device__ __forceinline__ void write2(int m, int n, float v0, float v1) const {
        v0 += bias[n]; v1 += bias[n+1];
        int b = m >> 11, s = m & 2047;
        int which = n >> 10, rest = n & 1023;
        int h = rest >> 6, dd = rest & 63;
        int bh = b*HH + h;
        if (which == 0) {
            *(uint32_t*)&g_qh[((size_t)bh*SS + s)*HD + dd] = pack_h2(v0, v1);
        } else if (which == 1) {
            *(uint32_t*)&g_kh[((size_t)bh*SS + s)*HD + dd] = pack_h2(v0, v1);
        } else {
            v0 += c_vadd[rest]; v1 += c_vadd[rest+1];
            g_vth[((size_t)bh*HD + dd)*SS + s]     = __float2half_rn(v0);
            g_vth[((size_t)bh*HD + dd + 1)*SS + s] = __float2half_rn(v1);
        }
    }
};

struct EpiOut {
    const float* bias;
    __device__ __forceinline__ void write2(int m, int n, float v0, float v1) const {
        float2 o = make_float2(v0 + bias[n], v1 + bias[n+1]);
        *(float2*)&g_proj[(size_t)m*DD + n] = o;
    }
};

__device__ __forceinline__ void ge_load(__half* dstA, __half* dstB,
                                        const __half* A, const __half* B,
                                        int m0, int n0, int k0, int t) {
    #pragma unroll
    for (int i = 0; i < 4; i++) {
        int f = t + i*256;
        int row = f >> 3, c = f & 7;
        cp16h(dstA + row*GE_STR + c*8, A + (size_t)(m0+row)*DD + k0 + c*8);
    }
    #pragma unroll
    for (int i = 0; i < 4; i++) {
        int f = t + i*256;
        int row = f >> 3, c = f & 7;
        cp16h(dstB + row*GE_STR + c*8, B + (size_t)(n0+row)*DD + k0 + c*8);
    }
}

template<typename Epi>
__global__ void __launch_bounds__(256) gemm_f16(
    const __half* __restrict__ A, const __half* __restrict__ B, Epi epi)
{
    extern __shared__ __half gsm[];
    __half* As[2] = { gsm,                gsm + 2*GE_TILE_H };
    __half* Bs[2] = { gsm + GE_TILE_H,    gsm + 3*GE_TILE_H };

    int t = threadIdx.x, lane = t & 31, warp = t >> 5;
    int q = lane >> 2, r = lane & 3;
    int wm = (warp >> 1) * 32;
    int wn = (warp & 1) * 64;
    int m0 = blockIdx.y * 128, n0 = blockIdx.x * 128;

    float acc[2][8][4] = {};

    ge_load(As[0], Bs[0], A, B, m0, n0, 0, t);
    cp_commit();

    for (int kt = 0; kt < DD/GE_BK; kt++) {
        int cur = kt & 1;
        if (kt + 1 < DD/GE_BK) {
            ge_load(As[cur^1], Bs[cur^1], A, B, m0, n0, (kt+1)*GE_BK, t);
            cp_commit();
            cp_wait1();
        } else {
            cp_wait0();
        }
        __syncthreads();

        const __half* as = As[cur];
        const __half* bs = Bs[cur];
        #pragma unroll
        for (int ks = 0; ks < 4; ks++) {
            uint32_t af[2][4];
            #pragma unroll
            for (int mi = 0; mi < 2; mi++) {
                int row = wm + mi*16 + q;
                af[mi][0] = *(const uint32_t*)&as[row*GE_STR + ks*16 + 2*r];
                af[mi][1] = *(const uint32_t*)&as[(row+8)*GE_STR + ks*16 + 2*r];
                af[mi][2] = *(const uint32_t*)&as[row*GE_STR + ks*16 + 2*r + 8];
                af[mi][3] = *(const uint32_t*)&as[(row+8)*GE_STR + ks*16 + 2*r + 8];
            }
            #pragma unroll
            for (int nj = 0; nj < 8; nj++) {
                int col = wn + nj*8 + q;
                uint32_t b0 = *(const uint32_t*)&bs[col*GE_STR + ks*16 + 2*r];
                uint32_t b1 = *(const uint32_t*)&bs[col*GE_STR + ks*16 + 2*r + 8];
                mma_f16(acc[0][nj], af[0], b0, b1);
                mma_f16(acc[1][nj], af[1], b0, b1);
            }
        }
        __syncthreads();
    }

    #pragma unroll
    for (int mi = 0; mi < 2; mi++)
        #pragma unroll
        for (int nj = 0; nj < 8; nj++) {
            int m = m0 + wm + mi*16 + q;
            int n = n0 + wn + nj*8 + 2*r;
            epi.write2(m,     n, acc[mi][nj][0], acc[mi][nj][1]);
            epi.write2(m + 8, n, acc[mi][nj][2], acc[mi][nj][3]);
        }
}

// ============================================================================
// Fused attention, fp16. Warp tile 32 rows x 64 keys (warps 4x2).
// Pass 1: S=QK^T (f16 mma) -> exp2 -> rowsum + O += P@V (C-frag -> A-frag direct).
// Pass 2: recompute S, write w = exp2(a*s + b - log2 l) to gmem.
// ============================================================================
#define QS_STR 72
#define VT_STR 136
#define Q_HALVES (128*QS_STR)     // 9216
#define VT_HALVES (64*VT_STR)     // 8704
#define ATT_SMEM_BYTES ((3*Q_HALVES + 2*VT_HALVES)*2)   // 90112

__device__ __forceinline__ void att_load_k(__half* dst, const __half* src, int t) {
    #pragma unroll
    for (int i = 0; i < 4; i++) {
        int f = t + i*256;
        int row = f >> 3, c = f & 7;
        cp16h(dst + row*QS_STR + c*8, src + (size_t)row*HD + c*8);
    }
}
__device__ __forceinline__ void att_load_vt(__half* dst, const __half* src, int t) {
    #pragma unroll
    for (int i = 0; i < 4; i++) {
        int f = t + i*256;
        int row = f >> 4, c = f & 15;
        cp16h(dst + row*VT_STR + c*8, src + (size_t)row*SS + c*8);
    }
}

__global__ void __launch_bounds__(256, 1) attn_fused(
    const __half* __restrict__ qg, const __half* __restrict__ kg,
    const __half* __restrict__ vtg, float* __restrict__ wout)
{
    extern __shared__ __half asm_[];
    __half* qs  = asm_;
    __half* ks0 = asm_ + Q_HALVES;
    __half* ks1 = asm_ + 2*Q_HALVES;
    __half* vt0 = asm_ + 3*Q_HALVES;
    __half* vt1 = asm_ + 3*Q_HALVES + VT_HALVES;
    __shared__ float l_part[2][128];

    int t = threadIdx.x, lane = t & 31, warp = t >> 5;
    int q = lane >> 2, r = lane & 3;
    int wr = warp >> 1, wc = warp & 1;
    int m0 = blockIdx.x*128, bh = blockIdx.y;
    int h = bh & 15, b = bh >> 4;
    const __half* Q  = qg  + ((size_t)bh*SS + m0)*HD;
    const __half* K  = kg  + (size_t)bh*SS*HD;
    const __half* Vt = vtg + (size_t)bh*HD*SS;
    const float LOG2E = 1.4426950408889634f;
    float al2 = c_alpha[h]*LOG2E, be2 = c_beta[h]*LOG2E;

    // load Q tile
    #pragma unroll
    for (int i = 0; i < 4; i++) {
        int f = t + i*256;
        int row = f >> 3, c = f & 7;
        *(uint4*)&qs[row*QS_STR + c*8] = *(const uint4*)(Q + (size_t)row*HD + c*8);
    }

    // prefetch tile 0
    att_load_k(ks0, K, t);
    att_load_vt(vt0, Vt, t);
    cp_commit();
    __syncthreads();

    // hoist Q fragments (fixed for whole kernel)
    uint32_t qf[2][4][4];
    #pragma unroll
    for (int mi = 0; mi < 2; mi++)
        #pragma unroll
        for (int ks = 0; ks < 4; ks++) {
            int row = wr*32 + mi*16 + q;
            qf[mi][ks][0] = *(const uint32_t*)&qs[row*QS_STR + ks*16 + 2*r];
            qf[mi][ks][1] = *(const uint32_t*)&qs[(row+8)*QS_STR + ks*16 + 2*r];
            qf[mi][ks][2] = *(const uint32_t*)&qs[row*QS_STR + ks*16 + 2*r + 8];
            qf[mi][ks][3] = *(const uint32_t*)&qs[(row+8)*QS_STR + ks*16 + 2*r + 8];
        }

    float O[2][8][4] = {};
    float rs[2][2] = {};

    // ---------------- pass 1 ----------------
    for (int kt = 0; kt < 16; kt++) {
        __half* kss = (kt & 1) ? ks1 : ks0;
        __half* vts = (kt & 1) ? vt1 : vt0;
        if (kt < 15) {
            att_load_k((kt & 1) ? ks0 : ks1, K + (size_t)(kt+1)*128*HD, t);
            att_load_vt((kt & 1) ? vt0 : vt1, Vt + (size_t)(kt+1)*128, t);
            cp_commit();
            cp_wait1();
        } else {
            cp_wait0();
        }
        __syncthreads();

        // ---- S = Q K^T ----
        float acc[2][8][4] = {};
        #pragma unroll
        for (int ks = 0; ks < 4; ks++) {
            #pragma unroll
            for (int nj = 0; nj < 8; nj++) {
                int key = wc*64 + nj*8 + q;
                uint32_t b0 = *(const uint32_t*)&kss[key*QS_STR + ks*16 + 2*r];
                uint32_t b1 = *(const uint32_t*)&kss[key*QS_STR + ks*16 + 2*r + 8];
                mma_f16(acc[0][nj], qf[0][ks], b0, b1);
                mma_f16(acc[1][nj], qf[1][ks], b0, b1);
            }
        }
        // ---- exp + rowsum ----
        #pragma unroll
        for (int mi = 0; mi < 2; mi++)
            #pragma unroll
            for (int nj = 0; nj < 8; nj++) {
                float e0 = fast_exp2(fmaf(al2, acc[mi][nj][0], be2));
                float e1 = fast_exp2(fmaf(al2, acc[mi][nj][1], be2));
                float e2 = fast_exp2(fmaf(al2, acc[mi][nj][2], be2));
                float e3 = fast_exp2(fmaf(al2, acc[mi][nj][3], be2));
                acc[mi][nj][0] = e0; acc[mi][nj][1] = e1;
                acc[mi][nj][2] = e2; acc[mi][nj][3] = e3;
                rs[mi][0] += e0 + e1;
                rs[mi][1] += e2 + e3;
            }
        // ---- O += P @ V : C-frag -> A-frag direct ----
        #pragma unroll
        for (int kk = 0; kk < 4; kk++) {
            uint32_t bf[8][2];
            #pragma unroll
            for (int nj = 0; nj < 8; nj++) {
                int hd = nj*8 + q;
                int key = wc*64 + kk*16 + 2*r;
                bf[nj][0] = *(const uint32_t*)&vts[hd*VT_STR + key];
                bf[nj][1] = *(const uint32_t*)&vts[hd*VT_STR + key + 8];
            }
            #pragma unroll
            for (int mi = 0; mi < 2; mi++) {
                uint32_t af[4];
                af[0] = pack_h2(acc[mi][2*kk][0],   acc[mi][2*kk][1]);
                af[1] = pack_h2(acc[mi][2*kk][2],   acc[mi][2*kk][3]);
                af[2] = pack_h2(acc[mi][2*kk+1][0], acc[mi][2*kk+1][1]);
                af[3] = pack_h2(acc[mi][2*kk+1][2], acc[mi][2*kk+1][3]);
                #pragma unroll
                for (int nj = 0; nj < 8; nj++)
                    mma_f16(O[mi][nj], af, bf[nj][0], bf[nj][1]);
            }
        }
        __syncthreads();
    }

    // ---------------- rowsum reduction ----------------
    #pragma unroll
    for (int mi = 0; mi < 2; mi++)
        #pragma unroll
        for (int j = 0; j < 2; j++) {
            rs[mi][j] += __shfl_xor_sync(0xffffffffu, rs[mi][j], 1);
            rs[mi][j] += __shfl_xor_sync(0xffffffffu, rs[mi][j], 2);
        }
    if (r == 0) {
        #pragma unroll
        for (int mi = 0; mi < 2; mi++)
            #pragma unroll
            for (int j = 0; j < 2; j++)
                l_part[wc][wr*32 + mi*16 + j*8 + q] = rs[mi][j];
    }
    __syncthreads();
    float inv[2][2], lg[2][2];
    #pragma unroll
    for (int mi = 0; mi < 2; mi++)
        #pragma unroll
        for (int j = 0; j < 2; j++) {
            int row = wr*32 + mi*16 + j*8 + q;
            float l = l_part[0][row] + l_part[1][row];
            inv[mi][j] = 1.0f / l;
            lg[mi][j] = __log2f(l);
        }

    // ---------------- O cross-warp reduction + store (half) ----------------
    float* scr = (float*)vt0;   // 32KB scratch over vt0+vt1 (34816B)
    if (wc == 1) {
        #pragma unroll
        for (int mi = 0; mi < 2; mi++)
            #pragma unroll
            for (int nj = 0; nj < 8; nj++)
                #pragma unroll
                for (int p = 0; p < 4; p++) {
                    int idx = (mi*8 + nj)*4 + p;
                    scr[(wr*64 + idx)*32 + lane] = O[mi][nj][p];
                }
    }
    __syncthreads();
    if (wc == 0) {
        #pragma unroll
        for (int mi = 0; mi < 2; mi++)
            #pragma unroll
            for (int nj = 0; nj < 8; nj++) {
                #pragma unroll
                for (int p = 0; p < 4; p++) {
                    int idx = (mi*8 + nj)*4 + p;
                    O[mi][nj][p] += scr[(wr*64 + idx)*32 + lane];
                }
                int row = m0 + wr*32 + mi*16 + q;
                int col = h*64 + nj*8 + 2*r;
                *(uint32_t*)&g_atth[((size_t)(b*SS + row))*DD + col] =
                    pack_h2(O[mi][nj][0]*inv[mi][0], O[mi][nj][1]*inv[mi][0]);
                *(uint32_t*)&g_atth[((size_t)(b*SS + row + 8))*DD + col] =
                    pack_h2(O[mi][nj][2]*inv[mi][1], O[mi][nj][3]*inv[mi][1]);
            }
    }
    __syncthreads();

    // ---------------- pass 2: recompute S, write normalized w ----------------
    float* wbh = wout + (size_t)bh*SS*SS;
    att_load_k(ks0, K, t);
    cp_commit();
    for (int kt = 0; kt < 16; kt++) {
        __half* kss = (kt & 1) ? ks1 : ks0;
        if (kt < 15) {
            att_load_k((kt & 1) ? ks0 : ks1, K + (size_t)(kt+1)*128*HD, t);
            cp_commit();
            cp_wait1();
        } else {
            cp_wait0();
        }
        __syncthreads();

        float acc[2][8][4] = {};
        #pragma unroll
        for (int ks = 0; ks < 4; ks++) {
            #pragma unroll
            for (int nj = 0; nj < 8; nj++) {
                int key = wc*64 + nj*8 + q;
                uint32_t b0 = *(const uint32_t*)&kss[key*QS_STR + ks*16 + 2*r];
                uint32_t b1 = *(const uint32_t*)&kss[key*QS_STR + ks*16 + 2*r + 8];
                mma_f16(acc[0][nj], qf[0][ks], b0, b1);
                mma_f16(acc[1][nj], qf[1][ks], b0, b1);
            }
        }
        #pragma unroll
        for (int mi = 0; mi < 2; mi++) {
            int row = m0 + wr*32 + mi*16 + q;
            float c0 = be2 - lg[mi][0], c1 = be2 - lg[mi][1];
            #pragma unroll
            for (int nj = 0; nj < 8; nj++) {
                int col = kt*128 + wc*64 + nj*8 + 2*r;
                float e0 = fast_exp2(fmaf(al2, acc[mi][nj][0], c0));
                float e1 = fast_exp2(fmaf(al2, acc[mi][nj][1], c0));
                float e2 = fast_exp2(fmaf(al2, acc[mi][nj][2], c1));
                float e3 = fast_exp2(fmaf(al2, acc[mi][nj][3], c1));
                __stcs((float2*)&wbh[(size_t)row*SS + col], make_float2(e0, e1));
                __stcs((float2*)&wbh[(size_t)(row+8)*SS + col], make_float2(e2, e3));
            }
        }
        __syncthreads();
    }
}

// ---------------- final: mix + LN-post ----------------
__global__ void final_kernel(const float* __restrict__ g, const float* __restrict__ b,
                             float* __restrict__ out) {
    __shared__ float red[256], red2[256];
    size_t row = blockIdx.x;
    int t = threadIdx.x;
    float gm = c_misc[1];
    float vals[4]; float s1 = 0.f, s2 = 0.f;
    #pragma unroll
    for (int l = 0; l < 4; l++) {
        size_t idx = row*DD + t + l*256;
        float vv = g_proj[idx]*gm + g_xn[idx]*(1.f - gm);
        vals[l] = vv; s1 += vv; s2 += vv*vv;
    }
    red[t] = s1; red2[t] = s2; __syncthreads();
    for (int off = 128; off > 0; off >>= 1) {
        if (t < off) { red[t] += red[t+off]; red2[t] += red2[t+off]; }
        __syncthreads();
    }
    float m = red[0]*(1.0f/DD);
    float var = red2[0]*(1.0f/DD) - m*m;
    float inv = rsqrtf(var + 1e-5f);
    #pragma unroll
    for (int l = 0; l < 4; l++) {
        int i = t + l*256;
        out[row*DD + i] = (vals[l]-m)*inv*g[i] + b[i];
    }
}

// ---------------------------------------------------------------------------
extern "C" void kernel_launch(void* const* d_in, const int* in_sizes, int n_in,
                              void* d_out, int out_size) {
    const float* x      = (const float*)d_in[0];
    const float* cf     = (const float*)d_in[1];
    const float* lnpg   = (const float*)d_in[2];
    const float* lnpb   = (const float*)d_in[3];
    const float* Wqkv   = (const float*)d_in[4];
    const float* bqkv   = (const float*)d_in[5];
    const float* eW1    = (const float*)d_in[6];
    const float* eb1    = (const float*)d_in[7];
    const float* eg1    = (const float*)d_in[8];
    const float* ebb1   = (const float*)d_in[9];
    const float* eW2    = (const float*)d_in[10];
    const float* eb2    = (const float*)d_in[11];
    const float* eg2    = (const float*)d_in[12];
    const float* ebb2   = (const float*)d_in[13];
    const float* Wga    = (const float*)d_in[14];
    const float* bga    = (const float*)d_in[15];
    const float* Wgv    = (const float*)d_in[16];
    const float* bgv    = (const float*)d_in[17];
    const float* Wt     = (const float*)d_in[18];
    const float* bt     = (const float*)d_in[19];
    const float* qrot   = (const float*)d_in[20];
    const float* fsc    = (const float*)d_in[21];
    const float* Wout   = (const float*)d_in[22];
    const float* bout   = (const float*)d_in[23];
    const float* lnqg   = (const float*)d_in[24];
    const float* lnqb   = (const float*)d_in[25];

    float* out = (float*)d_out;

    size_t need = (size_t)BS*DD + (size_t)BH*SS*SS;
    float* wbuf;
    if ((size_t)out_size >= need) {
        wbuf = out + (size_t)BS*DD;
    } else {
        float* wptr = nullptr;
        cudaGetSymbolAddress((void**)&wptr, g_w);
        wbuf = wptr;
    }

    __half *xnh_p, *qh_p, *kh_p, *vth_p, *atth_p, *wqkvh_p, *wouth_p;
    cudaGetSymbolAddress((void**)&xnh_p,   g_xnh);
    cudaGetSymbolAddress((void**)&qh_p,    g_qh);
    cudaGetSymbolAddress((void**)&kh_p,    g_kh);
    cudaGetSymbolAddress((void**)&vth_p,   g_vth);
    cudaGetSymbolAddress((void**)&atth_p,  g_atth);
    cudaGetSymbolAddress((void**)&wqkvh_p, g_wqkvh);
    cudaGetSymbolAddress((void**)&wouth_p, g_wouth);

    static bool attr_set = false;
    if (!attr_set) {
        cudaFuncSetAttribute(attn_fused,
                             cudaFuncAttributeMaxDynamicSharedMemorySize,
                             ATT_SMEM_BYTES);
        cudaFuncSetAttribute(gemm_f16<EpiQKV>,
                             cudaFuncAttributeMaxDynamicSharedMemorySize,
                             GE_SMEM_BYTES);
        cudaFuncSetAttribute(gemm_f16<EpiOut>,
                             cudaFuncAttributeMaxDynamicSharedMemorySize,
                             GE_SMEM_BYTES);
        attr_set = true;
    }

    chaos1_kernel<<<1, 256>>>(cf, eW1, eb1, eg1, ebb1, Wga, bga, Wgv, bgv, Wt, bt);
    chaos2_kernel<<<64, 256>>>(eW2, eb2);
    chaos3_kernel<<<1, 256>>>(eg2, ebb2, qrot, fsc);

    round_weights<<<(3*DD*DD + DD*DD)/(256*4), 256>>>(Wqkv, Wout);
    ln_pre_kernel<<<BS, 256>>>(x, lnpg, lnpb);

    // QKV: C[4096,3072] = xn @ Wqkv^T  (fp16 mma)
    gemm_f16<EpiQKV><<<dim3(3*DD/128, BS/128), 256, GE_SMEM_BYTES>>>(
        xnh_p, wqkvh_p, EpiQKV{bqkv});

    // fused attention
    attn_fused<<<dim3(SS/128, BH), 256, ATT_SMEM_BYTES>>>(qh_p, kh_p, vth_p, wbuf);

    // out projection: C[4096,1024] = att @ Wout^T  (fp16 mma)
    gemm_f16<EpiOut><<<dim3(DD/128, BS/128), 256, GE_SMEM_BYTES>>>(
        atth_p, wouth_p, EpiOut{bout});

    final_kernel<<<BS, 256>>>(lnqg, lnqb, out);
}

// round 6
// speedup vs baseline: 7.1184x; 1.0969x over previous
#include <cuda_runtime.h>
#include <cuda_fp16.h>
#include <math.h>
#include <stdint.h>

#define BB 2
#define SS 2048
#define DD 1024
#define HH 16
#define HD 64
#define CC 16
#define BS (BB*SS)
#define BH (BB*HH)

// ---------------- device scratch ----------------
__device__ __align__(256) float  g_xn[BS*DD];
__device__ __align__(256) __half g_xnh[BS*DD];
__device__ __align__(256) __half g_qh[BH*SS*HD];
__device__ __align__(256) __half g_kh[BH*SS*HD];
__device__ __align__(256) __half g_vth[BH*HD*SS];       // V transposed: [bh][hd][s]
__device__ __align__(256) __half g_atth[BS*DD];
__device__ __align__(256) float  g_proj[BS*DD];
__device__ __align__(256) __half g_wqkvh[3*DD*DD];
__device__ __align__(256) __half g_wouth[DD*DD];
__device__ __align__(256) float  g_l[BH*SS];            // row sums from pass1
__device__ __align__(256) float  g_w[(size_t)BH*SS*SS]; // fallback w buffer

__device__ float c_h1[DD];
__device__ float c_cepre[DD];
__device__ float c_gate_a[HH];
__device__ float c_gate_v[HH];
__device__ float c_misc[2];
__device__ float c_alpha[HH];
__device__ float c_beta[HH];
__device__ float c_vadd[DD];

// ---------------- helpers ----------------
__device__ __forceinline__ uint32_t pack_h2(float a, float b) {
    __half2 h = __floats2half2_rn(a, b);
    return *reinterpret_cast<uint32_t*>(&h);
}

__device__ __forceinline__ float fast_exp2(float x) {
    float z = x + 12582912.0f;
    int   i = __float_as_int(z);
    float f = x - (z - 12582912.0f);
    float p = 9.618129e-3f;
    p = fmaf(p, f, 5.5504109e-2f);
    p = fmaf(p, f, 2.4022651e-1f);
    p = fmaf(p, f, 6.9314718e-1f);
    p = fmaf(p, f, 1.0f);
    return __int_as_float(__float_as_int(p) + (i << 23));
}

__device__ __forceinline__ void mma_f16(float c[4], const uint32_t a[4],
                                        uint32_t b0, uint32_t b1) {
    asm volatile(
        "mma.sync.aligned.m16n8k16.row.col.f32.f16.f16.f32 "
        "{%0,%1,%2,%3}, {%4,%5,%6,%7}, {%8,%9}, {%0,%1,%2,%3};"
        : "+f"(c[0]), "+f"(c[1]), "+f"(c[2]), "+f"(c[3])
        : "r"(a[0]), "r"(a[1]), "r"(a[2]), "r"(a[3]), "r"(b0), "r"(b1));
}

__device__ __forceinline__ uint32_t lds_addr(const void* p) {
    return (uint32_t)__cvta_generic_to_shared(p);
}
__device__ __forceinline__ void ldsm4(uint32_t r[4], uint32_t a) {
    asm volatile("ldmatrix.sync.aligned.m8n8.x4.shared.b16 {%0,%1,%2,%3}, [%4];"
                 : "=r"(r[0]), "=r"(r[1]), "=r"(r[2]), "=r"(r[3]) : "r"(a));
}

__device__ __forceinline__ void cp16h(__half* dst, const __half* src) {
    unsigned d = (unsigned)__cvta_generic_to_shared(dst);
    asm volatile("cp.async.cg.shared.global [%0], [%1], 16;" :: "r"(d), "l"(src));
}
__device__ __forceinline__ void cp_commit() { asm volatile("cp.async.commit_group;"); }
__device__ __forceinline__ void cp_wait1() { asm volatile("cp.async.wait_group 1;"); }
__device__ __forceinline__ void cp_wait0() { asm volatile("cp.async.wait_group 0;"); }

// ---------------- chaos encoder ----------------
__global__ void chaos1_kernel(const float* __restrict__ cf,
                              const float* __restrict__ W1, const float* __restrict__ b1,
                              const float* __restrict__ g1, const float* __restrict__ bb1,
                              const float* __restrict__ Wga, const float* __restrict__ bga,
                              const float* __restrict__ Wgv, const float* __restrict__ bgv,
                              const float* __restrict__ Wt,  const float* __restrict__ bt) {
    __shared__ float cfs[CC];
    __shared__ float red[256], red2[256];
    int t = threadIdx.x;
    if (t < CC) cfs[t] = cf[t];
    __syncthreads();

    if (t < HH) {
        float sa = bga[t], sv = bgv[t];
        #pragma unroll
        for (int c = 0; c < CC; c++) { sa += cfs[c]*Wga[t*CC+c]; sv += cfs[c]*Wgv[t*CC+c]; }
        c_gate_a[t] = 1.f/(1.f+expf(-sa));
        c_gate_v[t] = 1.f/(1.f+expf(-sv));
    } else if (t == 16) {
        float s = bt[0];
        #pragma unroll
        for (int c = 0; c < CC; c++) s += cfs[c]*Wt[c];
        float sp = (s > 20.f) ? s : log1pf(expf(s));
        c_misc[0] = sp + 1.0f;
    } else if (t == 17) {
        float s = 0.f;
        #pragma unroll
        for (int c = 0; c < CC; c++) s += cfs[c];
        s *= (1.0f/CC);
        c_misc[1] = (1.f/(1.f+expf(-s)))*0.5f + 0.5f;
    }

    float vals[4];
    float s1 = 0.f, s2 = 0.f;
    #pragma unroll
    for (int l = 0; l < 4; l++) {
        int i = t*4 + l;
        float a = b1[i];
        #pragma unroll
        for (int c = 0; c < CC; c++) a += cfs[c]*W1[i*CC+c];
        vals[l] = a; s1 += a; s2 += a*a;
    }
    red[t] = s1; red2[t] = s2; __syncthreads();
    for (int o = 128; o > 0; o >>= 1) {
        if (t < o) { red[t] += red[t+o]; red2[t] += red2[t+o]; }
        __syncthreads();
    }
    float m = red[0]*(1.0f/DD);
    float var = red2[0]*(1.0f/DD) - m*m;
    float inv = rsqrtf(var + 1e-5f);
    #pragma unroll
    for (int l = 0; l < 4; l++) {
        int i = t*4 + l;
        float h = (vals[l]-m)*inv*g1[i] + bb1[i];
        c_h1[i] = fmaxf(h, 0.f);
    }
}

__global__ void chaos2_kernel(const float* __restrict__ W2, const float* __restrict__ b2) {
    __shared__ float h1s[DD];
    __shared__ float red[256];
    int t = threadIdx.x;
    #pragma unroll
    for (int l = 0; l < 4; l++) h1s[t + l*256] = c_h1[t + l*256];
    __syncthreads();
    int r = t >> 4, c = t & 15;
    int i = blockIdx.x*16 + r;
    float s = 0.f;
    for (int j = c; j < DD; j += 16) s += h1s[j]*W2[(size_t)i*DD + j];
    red[t] = s; __syncthreads();
    for (int o = 8; o > 0; o >>= 1) {
        if (c < o) red[t] += red[t+o];
        __syncthreads();
    }
    if (c == 0) c_cepre[i] = red[r*16] + b2[i];
}

__global__ void chaos3_kernel(const float* __restrict__ g2, const float* __restrict__ bb2,
                              const float* __restrict__ qrot, const float* __restrict__ fscales) {
    __shared__ float ce[DD];
    __shared__ float scs[DD];
    __shared__ float red[256], red2[256];
    int t = threadIdx.x;
    float vals[4]; float s1 = 0.f, s2 = 0.f;
    #pragma unroll
    for (int l = 0; l < 4; l++) {
        int i = t + l*256;
        vals[l] = c_cepre[i]; s1 += vals[l]; s2 += vals[l]*vals[l];
    }
    red[t] = s1; red2[t] = s2; __syncthreads();
    for (int o = 128; o > 0; o >>= 1) {
        if (t < o) { red[t] += red[t+o]; red2[t] += red2[t+o]; }
        __syncthreads();
    }
    float m = red[0]*(1.0f/DD);
    float var = red2[0]*(1.0f/DD) - m*m;
    float inv = rsqrtf(var + 1e-5f);
    #pragma unroll
    for (int l = 0; l < 4; l++) {
        int i = t + l*256;
        ce[i] = (vals[l]-m)*inv*g2[i] + bb2[i];
    }
    __syncthreads();
    float sfs = 1.f/(1.f+expf(-fscales[0]));
    #pragma unroll
    for (int l = 0; l < 4; l++) {
        int i = t + l*256;
        int h = i >> 6, d = i & 63;
        float s = 0.f;
        #pragma unroll 8
        for (int e = 0; e < HD; e++) s += ce[h*HD+e]*qrot[e*HD+d];
        s *= sfs;
        scs[i] = s;
        c_vadd[i] = s * c_gate_v[h];
    }
    __syncthreads();
    if (t < HH) {
        float bsum = 0.f;
        for (int d = 0; d < HD; d++) bsum += scs[t*HD + d];
        float temp = c_misc[0];
        c_alpha[t] = c_gate_a[t]/(8.f*temp);
        c_beta[t]  = bsum/temp;
    }
}

// ---------------- LN-pre ----------------
__global__ void ln_pre_kernel(const float* __restrict__ x,
                              const float* __restrict__ g, const float* __restrict__ b) {
    __shared__ float red[256], red2[256];
    size_t row = blockIdx.x;
    const float4* xr = (const float4*)(x + row*DD);
    int t = threadIdx.x;
    float4 v = xr[t];
    float s1 = v.x + v.y + v.z + v.w;
    float s2 = v.x*v.x + v.y*v.y + v.z*v.z + v.w*v.w;
    red[t] = s1; red2[t] = s2; __syncthreads();
    for (int off = 128; off > 0; off >>= 1) {
        if (t < off) { red[t] += red[t+off]; red2[t] += red2[t+off]; }
        __syncthreads();
    }
    float m = red[0]*(1.0f/DD);
    float var = red2[0]*(1.0f/DD) - m*m;
    float inv = rsqrtf(var + 1e-5f);
    int i = t*4;
    float4 gg = *(const float4*)(g + i);
    float4 bb = *(const float4*)(b + i);
    float4 o;
    o.x = (v.x-m)*inv*gg.x + bb.x;
    o.y = (v.y-m)*inv*gg.y + bb.y;
    o.z = (v.z-m)*inv*gg.z + bb.z;
    o.w = (v.w-m)*inv*gg.w + bb.w;
    *(float4*)(g_xn + row*DD + i) = o;
    uint2 h;
    h.x = pack_h2(o.x, o.y);
    h.y = pack_h2(o.z, o.w);
    *(uint2*)(g_xnh + row*DD + i) = h;
}

// ---------------- convert weights to half ----------------
__global__ void round_weights(const float* __restrict__ Wqkv,
                              const float* __restrict__ Wout) {
    size_t i = (size_t)blockIdx.x*256 + threadIdx.x;
    const size_t nqkv = (size_t)3*DD*DD/4;
    float4 v;
    __half* dst;
    if (i < nqkv) {
        v = ((const float4*)Wqkv)[i];
        dst = g_wqkvh + i*4;
    } else {
        v = ((const float4*)Wout)[i - nqkv];
        dst = g_wouth + (i - nqkv)*4;
    }
    uint2 h;
    h.x = pack_h2(v.x, v.y);
    h.y = pack_h2(v.z, v.w);
    *(uint2*)dst = h;
}

// ============================================================================
// fp16 tensor-core GEMM (NT) with ldmatrix fragment loads.
// ============================================================================
#define GE_BK 64
#define GE_STR 72
#define GE_TILE_H (128*GE_STR)
#define GE_SMEM_BYTES (4*GE_TILE_H*2)

struct EpiQKV {
    const float* bias;
    __device__ __forceinline__ void write2(int m, int n, float v0, float v1) const {
        v0 += bias[n]; v1 += bias[n+1];
        int b = m >> 11, s = m & 2047;
        int which = n >> 10, rest = n & 1023;
        int h = rest >> 6, dd = rest & 63;
        int bh = b*HH + h;
        if (which == 0) {
            *(uint32_t*)&g_qh[((size_t)bh*SS + s)*HD + dd] = pack_h2(v0, v1);
        } else if (which == 1) {
            *(uint32_t*)&g_kh[((size_t)bh*SS + s)*HD + dd] = pack_h2(v0, v1);
        } else {
            v0 += c_vadd[rest]; v1 += c_vadd[rest+1];
            g_vth[((size_t)bh*HD + dd)*SS + s]     = __float2half_rn(v0);
            g_vth[((size_t)bh*HD + dd + 1)*SS + s] = __float2half_rn(v1);
        }
    }
};

struct EpiOut {
    const float* bias;
    __device__ __forceinline__ void write2(int m, int n, float v0, float v1) const {
        float2 o = make_float2(v0 + bias[n], v1 + bias[n+1]);
        *(float2*)&g_proj[(size_t)m*DD + n] = o;
    }
};

__device__ __forceinline__ void ge_load(__half* dstA, __half* dstB,
                                        const __half* A, const __half* B,
                                        int m0, int n0, int k0, int t) {
    #pragma unroll
    for (int i = 0; i < 4; i++) {
        int f = t + i*256;
        int row = f >> 3, c = f & 7;
        cp16h(dstA + row*GE_STR + c*8, A + (size_t)(m0+row)*DD + k0 + c*8);
    }
    #pragma unroll
    for (int i = 0; i < 4; i++) {
        int f = t + i*256;
        int row = f >> 3, c = f & 7;
        cp16h(dstB + row*GE_STR + c*8, B + (size_t)(n0+row)*DD + k0 + c*8);
    }
}

template<typename Epi>
__global__ void __launch_bounds__(256) gemm_f16(
    const __half* __restrict__ A, const __half* __restrict__ B, Epi epi)
{
    extern __shared__ __half gsm[];
    __half* As[2] = { gsm,                gsm + 2*GE_TILE_H };
    __half* Bs[2] = { gsm + GE_TILE_H,    gsm + 3*GE_TILE_H };

    int t = threadIdx.x, lane = t & 31, warp = t >> 5;
    int q = lane >> 2, r = lane & 3;
    int wm = (warp >> 1) * 32;
    int wn = (warp & 1) * 64;
    int m0 = blockIdx.y * 128, n0 = blockIdx.x * 128;

    // ldmatrix per-lane half-offsets
    int a_off = (wm + (lane & 15))*GE_STR + (lane >> 4)*8;
    int b_off = (wn + (lane & 7) + ((lane & 16) >> 1))*GE_STR + (lane & 8);

    float acc[2][8][4] = {};

    ge_load(As[0], Bs[0], A, B, m0, n0, 0, t);
    cp_commit();

    for (int kt = 0; kt < DD/GE_BK; kt++) {
        int cur = kt & 1;
        if (kt + 1 < DD/GE_BK) {
            ge_load(As[cur^1], Bs[cur^1], A, B, m0, n0, (kt+1)*GE_BK, t);
            cp_commit();
            cp_wait1();
        } else {
            cp_wait0();
        }
        __syncthreads();

        uint32_t asb = lds_addr(As[cur]);
        uint32_t bsb = lds_addr(Bs[cur]);
        #pragma unroll
        for (int ks = 0; ks < 4; ks++) {
            uint32_t af[2][4];
            ldsm4(af[0], asb + 2*(a_off + ks*16));
            ldsm4(af[1], asb + 2*(a_off + 16*GE_STR + ks*16));
            #pragma unroll
            for (int p = 0; p < 4; p++) {
                uint32_t bb[4];
                ldsm4(bb, bsb + 2*(b_off + p*16*GE_STR + ks*16));
                mma_f16(acc[0][2*p],   af[0], bb[0], bb[1]);
                mma_f16(acc[0][2*p+1], af[0], bb[2], bb[3]);
                mma_f16(acc[1][2*p],   af[1], bb[0], bb[1]);
                mma_f16(acc[1][2*p+1], af[1], bb[2], bb[3]);
            }
        }
        __syncthreads();
    }

    #pragma unroll
    for (int mi = 0; mi < 2; mi++)
        #pragma unroll
        for (int nj = 0; nj < 8; nj++) {
            int m = m0 + wm + mi*16 + q;
            int n = n0 + wn + nj*8 + 2*r;
            epi.write2(m,     n, acc[mi][nj][0], acc[mi][nj][1]);
            epi.write2(m + 8, n, acc[mi][nj][2], acc[mi][nj][3]);
        }
}

// ============================================================================
// Attention pass 1: S=QK^T -> exp2 -> rowsum + O += P@V.  Stores O and g_l.
// ============================================================================
#define QS_STR 72
#define VT_STR 136
#define Q_HALVES (128*QS_STR)
#define VT_HALVES (64*VT_STR)
#define ATT_SMEM_BYTES ((3*Q_HALVES + 2*VT_HALVES)*2)   // 90112
#define P2_SMEM_BYTES (3*Q_HALVES*2)                    // 55296

__device__ __forceinline__ void att_load_k(__half* dst, const __half* src, int t) {
    #pragma unroll
    for (int i = 0; i < 4; i++) {
        int f = t + i*256;
        int row = f >> 3, c = f & 7;
        cp16h(dst + row*QS_STR + c*8, src + (size_t)row*HD + c*8);
    }
}
__device__ __forceinline__ void att_load_vt(__half* dst, const __half* src, int t) {
    #pragma unroll
    for (int i = 0; i < 4; i++) {
        int f = t + i*256;
        int row = f >> 4, c = f & 15;
        cp16h(dst + row*VT_STR + c*8, src + (size_t)row*SS + c*8);
    }
}

__global__ void __launch_bounds__(256, 1) attn_pass1(
    const __half* __restrict__ qg, const __half* __restrict__ kg,
    const __half* __restrict__ vtg)
{
    extern __shared__ __half asm_[];
    __half* qs  = asm_;
    __half* ks0 = asm_ + Q_HALVES;
    __half* ks1 = asm_ + 2*Q_HALVES;
    __half* vt0 = asm_ + 3*Q_HALVES;
    __half* vt1 = asm_ + 3*Q_HALVES + VT_HALVES;
    __shared__ float l_part[2][128];

    int t = threadIdx.x, lane = t & 31, warp = t >> 5;
    int q = lane >> 2, r = lane & 3;
    int wr = warp >> 1, wc = warp & 1;
    int m0 = blockIdx.x*128, bh = blockIdx.y;
    int h = bh & 15, b = bh >> 4;
    const __half* Q  = qg  + ((size_t)bh*SS + m0)*HD;
    const __half* K  = kg  + (size_t)bh*SS*HD;
    const __half* Vt = vtg + (size_t)bh*HD*SS;
    const float LOG2E = 1.4426950408889634f;
    float al2 = c_alpha[h]*LOG2E, be2 = c_beta[h]*LOG2E;

    #pragma unroll
    for (int i = 0; i < 4; i++) {
        int f = t + i*256;
        int row = f >> 3, c = f & 7;
        *(uint4*)&qs[row*QS_STR + c*8] = *(const uint4*)(Q + (size_t)row*HD + c*8);
    }

    att_load_k(ks0, K, t);
    att_load_vt(vt0, Vt, t);
    cp_commit();
    __syncthreads();

    // hoist Q fragments via ldmatrix
    uint32_t qf[2][4][4];
    {
        uint32_t qsb = lds_addr(qs);
        int q_off = (wr*32 + (lane & 15))*QS_STR + (lane >> 4)*8;
        #pragma unroll
        for (int mi = 0; mi < 2; mi++)
            #pragma unroll
            for (int ks = 0; ks < 4; ks++)
                ldsm4(qf[mi][ks], qsb + 2*(q_off + mi*16*QS_STR + ks*16));
    }

    int k_off = (wc*64 + (lane & 7) + ((lane & 16) >> 1))*QS_STR + (lane & 8);
    int v_off = ((lane & 7) + ((lane & 16) >> 1))*VT_STR + wc*64 + (lane & 8);

    float O[2][8][4] = {};
    float rs[2][2] = {};

    for (int kt = 0; kt < 16; kt++) {
        __half* kss = (kt & 1) ? ks1 : ks0;
        __half* vts = (kt & 1) ? vt1 : vt0;
        if (kt < 15) {
            att_load_k((kt & 1) ? ks0 : ks1, K + (size_t)(kt+1)*128*HD, t);
            att_load_vt((kt & 1) ? vt0 : vt1, Vt + (size_t)(kt+1)*128, t);
            cp_commit();
            cp_wait1();
        } else {
            cp_wait0();
        }
        __syncthreads();

        // ---- S = Q K^T ----
        float acc[2][8][4] = {};
        uint32_t ksb = lds_addr(kss);
        #pragma unroll
        for (int ks = 0; ks < 4; ks++) {
            #pragma unroll
            for (int p = 0; p < 4; p++) {
                uint32_t bb[4];
                ldsm4(bb, ksb + 2*(k_off + p*16*QS_STR + ks*16));
                mma_f16(acc[0][2*p],   qf[0][ks], bb[0], bb[1]);
                mma_f16(acc[0][2*p+1], qf[0][ks], bb[2], bb[3]);
                mma_f16(acc[1][2*p],   qf[1][ks], bb[0], bb[1]);
                mma_f16(acc[1][2*p+1], qf[1][ks], bb[2], bb[3]);
            }
        }
        // ---- exp + rowsum ----
        #pragma unroll
        for (int mi = 0; mi < 2; mi++)
            #pragma unroll
            for (int nj = 0; nj < 8; nj++) {
                float e0 = fast_exp2(fmaf(al2, acc[mi][nj][0], be2));
                float e1 = fast_exp2(fmaf(al2, acc[mi][nj][1], be2));
                float e2 = fast_exp2(fmaf(al2, acc[mi][nj][2], be2));
                float e3 = fast_exp2(fmaf(al2, acc[mi][nj][3], be2));
                acc[mi][nj][0] = e0; acc[mi][nj][1] = e1;
                acc[mi][nj][2] = e2; acc[mi][nj][3] = e3;
                rs[mi][0] += e0 + e1;
                rs[mi][1] += e2 + e3;
            }
        // ---- O += P @ V ----
        uint32_t vsb = lds_addr(vts);
        #pragma unroll
        for (int kk = 0; kk < 4; kk++) {
            uint32_t af[2][4];
            #pragma unroll
            for (int mi = 0; mi < 2; mi++) {
                af[mi][0] = pack_h2(acc[mi][2*kk][0],   acc[mi][2*kk][1]);
                af[mi][1] = pack_h2(acc[mi][2*kk][2],   acc[mi][2*kk][3]);
                af[mi][2] = pack_h2(acc[mi][2*kk+1][0], acc[mi][2*kk+1][1]);
                af[mi][3] = pack_h2(acc[mi][2*kk+1][2], acc[mi][2*kk+1][3]);
            }
            #pragma unroll
            for (int p = 0; p < 4; p++) {
                uint32_t bb[4];
                ldsm4(bb, vsb + 2*(v_off + p*16*VT_STR + kk*16));
                mma_f16(O[0][2*p],   af[0], bb[0], bb[1]);
                mma_f16(O[0][2*p+1], af[0], bb[2], bb[3]);
                mma_f16(O[1][2*p],   af[1], bb[0], bb[1]);
                mma_f16(O[1][2*p+1], af[1], bb[2], bb[3]);
            }
        }
        __syncthreads();
    }

    // ---- rowsum reduction ----
    #pragma unroll
    for (int mi = 0; mi < 2; mi++)
        #pragma unroll
        for (int j = 0; j < 2; j++) {
            rs[mi][j] += __shfl_xor_sync(0xffffffffu, rs[mi][j], 1);
            rs[mi][j] += __shfl_xor_sync(0xffffffffu, rs[mi][j], 2);
        }
    if (r == 0) {
        #pragma unroll
        for (int mi = 0; mi < 2; mi++)
            #pragma unroll
            for (int j = 0; j < 2; j++)
                l_part[wc][wr*32 + mi*16 + j*8 + q] = rs[mi][j];
    }
    __syncthreads();
    float inv[2][2];
    #pragma unroll
    for (int mi = 0; mi < 2; mi++)
        #pragma unroll
        for (int j = 0; j < 2; j++) {
            int row = wr*32 + mi*16 + j*8 + q;
            float l = l_part[0][row] + l_part[1][row];
            inv[mi][j] = 1.0f / l;
            if (wc == 0 && r == 0)
                g_l[(size_t)bh*SS + m0 + row] = l;
        }

    // ---- O cross-warp reduction + store (half) ----
    float* scr = (float*)vt0;
    if (wc == 1) {
        #pragma unroll
        for (int mi = 0; mi < 2; mi++)
            #pragma unroll
            for (int nj = 0; nj < 8; nj++)
                #pragma unroll
                for (int p = 0; p < 4; p++) {
                    int idx = (mi*8 + nj)*4 + p;
                    scr[(wr*64 + idx)*32 + lane] = O[mi][nj][p];
                }
    }
    __syncthreads();
    if (wc == 0) {
        #pragma unroll
        for (int mi = 0; mi < 2; mi++)
            #pragma unroll
            for (int nj = 0; nj < 8; nj++) {
                #pragma unroll
                for (int p = 0; p < 4; p++) {
                    int idx = (mi*8 + nj)*4 + p;
                    O[mi][nj][p] += scr[(wr*64 + idx)*32 + lane];
                }
                int row = m0 + wr*32 + mi*16 + q;
                int col = h*64 + nj*8 + 2*r;
                *(uint32_t*)&g_atth[((size_t)(b*SS + row))*DD + col] =
                    pack_h2(O[mi][nj][0]*inv[mi][0], O[mi][nj][1]*inv[mi][0]);
                *(uint32_t*)&g_atth[((size_t)(b*SS + row + 8))*DD + col] =
                    pack_h2(O[mi][nj][2]*inv[mi][1], O[mi][nj][3]*inv[mi][1]);
            }
    }
}

// ============================================================================
// Attention pass 2: recompute S, write w = exp2(a*s + b - log2 l).
// Standalone, occupancy 2/SM; runs concurrently with out-proj.
// ============================================================================
__global__ void __launch_bounds__(256, 2) attn_pass2(
    const __half* __restrict__ qg, const __half* __restrict__ kg,
    float* __restrict__ wout)
{
    extern __shared__ __half asm2_[];
    __half* qs  = asm2_;
    __half* ks0 = asm2_ + Q_HALVES;
    __half* ks1 = asm2_ + 2*Q_HALVES;

    int t = threadIdx.x, lane = t & 31, warp = t >> 5;
    int q = lane >> 2, r = lane & 3;
    int wr = warp >> 1, wc = warp & 1;
    int m0 = blockIdx.x*128, bh = blockIdx.y;
    int h = bh & 15;
    const __half* Q  = qg  + ((size_t)bh*SS + m0)*HD;
    const __half* K  = kg  + (size_t)bh*SS*HD;
    const float LOG2E = 1.4426950408889634f;
    float al2 = c_alpha[h]*LOG2E, be2 = c_beta[h]*LOG2E;

    #pragma unroll
    for (int i = 0; i < 4; i++) {
        int f = t + i*256;
        int row = f >> 3, c = f & 7;
        *(uint4*)&qs[row*QS_STR + c*8] = *(const uint4*)(Q + (size_t)row*HD + c*8);
    }
    att_load_k(ks0, K, t);
    cp_commit();

    // per-row constants: c = be2 - log2(l)
    float cc[2][2];
    #pragma unroll
    for (int mi = 0; mi < 2; mi++)
        #pragma unroll
        for (int j = 0; j < 2; j++) {
            int row = wr*32 + mi*16 + j*8 + q;
            cc[mi][j] = be2 - __log2f(g_l[(size_t)bh*SS + m0 + row]);
        }
    __syncthreads();

    uint32_t qf[2][4][4];
    {
        uint32_t qsb = lds_addr(qs);
        int q_off = (wr*32 + (lane & 15))*QS_STR + (lane >> 4)*8;
        #pragma unroll
        for (int mi = 0; mi < 2; mi++)
            #pragma unroll
            for (int ks = 0; ks < 4; ks++)
                ldsm4(qf[mi][ks], qsb + 2*(q_off + mi*16*QS_STR + ks*16));
    }
    int k_off = (wc*64 + (lane & 7) + ((lane & 16) >> 1))*QS_STR + (lane & 8);

    float* wbh = wout + (size_t)bh*SS*SS;
    for (int kt = 0; kt < 16; kt++) {
        __half* kss = (kt & 1) ? ks1 : ks0;
        if (kt < 15) {
            att_load_k((kt & 1) ? ks0 : ks1, K + (size_t)(kt+1)*128*HD, t);
            cp_commit();
            cp_wait1();
        } else {
            cp_wait0();
        }
        __syncthreads();

        float acc[2][8][4] = {};
        uint32_t ksb = lds_addr(kss);
        #pragma unroll
        for (int ks = 0; ks < 4; ks++) {
            #pragma unroll
            for (int p = 0; p < 4; p++) {
                uint32_t bb[4];
                ldsm4(bb, ksb + 2*(k_off + p*16*QS_STR + ks*16));
                mma_f16(acc[0][2*p],   qf[0][ks], bb[0], bb[1]);
                mma_f16(acc[0][2*p+1], qf[0][ks], bb[2], bb[3]);
                mma_f16(acc[1][2*p],   qf[1][ks], bb[0], bb[1]);
                mma_f16(acc[1][2*p+1], qf[1][ks], bb[2], bb[3]);
            }
        }
        #pragma unroll
        for (int mi = 0; mi < 2; mi++) {
            int row = m0 + wr*32 + mi*16 + q;
            #pragma unroll
            for (int nj = 0; nj < 8; nj++) {
                int col = kt*128 + wc*64 + nj*8 + 2*r;
                float e0 = fast_exp2(fmaf(al2, acc[mi][nj][0], cc[mi][0]));
                float e1 = fast_exp2(fmaf(al2, acc[mi][nj][1], cc[mi][0]));
                float e2 = fast_exp2(fmaf(al2, acc[mi][nj][2], cc[mi][1]));
                float e3 = fast_exp2(fmaf(al2, acc[mi][nj][3], cc[mi][1]));
                __stcs((float2*)&wbh[(size_t)row*SS + col], make_float2(e0, e1));
                __stcs((float2*)&wbh[(size_t)(row+8)*SS + col], make_float2(e2, e3));
            }
        }
        __syncthreads();
    }
}

// ---------------- final: mix + LN-post ----------------
__global__ void final_kernel(const float* __restrict__ g, const float* __restrict__ b,
                             float* __restrict__ out) {
    __shared__ float red[256], red2[256];
    size_t row = blockIdx.x;
    int t = threadIdx.x;
    float gm = c_misc[1];
    float vals[4]; float s1 = 0.f, s2 = 0.f;
    #pragma unroll
    for (int l = 0; l < 4; l++) {
        size_t idx = row*DD + t + l*256;
        float vv = g_proj[idx]*gm + g_xn[idx]*(1.f - gm);
        vals[l] = vv; s1 += vv; s2 += vv*vv;
    }
    red[t] = s1; red2[t] = s2; __syncthreads();
    for (int off = 128; off > 0; off >>= 1) {
        if (t < off) { red[t] += red[t+off]; red2[t] += red2[t+off]; }
        __syncthreads();
    }
    float m = red[0]*(1.0f/DD);
    float var = red2[0]*(1.0f/DD) - m*m;
    float inv = rsqrtf(var + 1e-5f);
    #pragma unroll
    for (int l = 0; l < 4; l++) {
        int i = t + l*256;
        out[row*DD + i] = (vals[l]-m)*inv*g[i] + b[i];
    }
}

// ---------------------------------------------------------------------------
extern "C" void kernel_launch(void* const* d_in, const int* in_sizes, int n_in,
                              void* d_out, int out_size) {
    const float* x      = (const float*)d_in[0];
    const float* cf     = (const float*)d_in[1];
    const float* lnpg   = (const float*)d_in[2];
    const float* lnpb   = (const float*)d_in[3];
    const float* Wqkv   = (const float*)d_in[4];
    const float* bqkv   = (const float*)d_in[5];
    const float* eW1    = (const float*)d_in[6];
    const float* eb1    = (const float*)d_in[7];
    const float* eg1    = (const float*)d_in[8];
    const float* ebb1   = (const float*)d_in[9];
    const float* eW2    = (const float*)d_in[10];
    const float* eb2    = (const float*)d_in[11];
    const float* eg2    = (const float*)d_in[12];
    const float* ebb2   = (const float*)d_in[13];
    const float* Wga    = (const float*)d_in[14];
    const float* bga    = (const float*)d_in[15];
    const float* Wgv    = (const float*)d_in[16];
    const float* bgv    = (const float*)d_in[17];
    const float* Wt     = (const float*)d_in[18];
    const float* bt     = (const float*)d_in[19];
    const float* qrot   = (const float*)d_in[20];
    const float* fsc    = (const float*)d_in[21];
    const float* Wout   = (const float*)d_in[22];
    const float* bout   = (const float*)d_in[23];
    const float* lnqg   = (const float*)d_in[24];
    const float* lnqb   = (const float*)d_in[25];

    float* out = (float*)d_out;

    size_t need = (size_t)BS*DD + (size_t)BH*SS*SS;
    float* wbuf;
    if ((size_t)out_size >= need) {
        wbuf = out + (size_t)BS*DD;
    } else {
        float* wptr = nullptr;
        cudaGetSymbolAddress((void**)&wptr, g_w);
        wbuf = wptr;
    }

    __half *xnh_p, *qh_p, *kh_p, *vth_p, *atth_p, *wqkvh_p, *wouth_p;
    cudaGetSymbolAddress((void**)&xnh_p,   g_xnh);
    cudaGetSymbolAddress((void**)&qh_p,    g_qh);
    cudaGetSymbolAddress((void**)&kh_p,    g_kh);
    cudaGetSymbolAddress((void**)&vth_p,   g_vth);
    cudaGetSymbolAddress((void**)&atth_p,  g_atth);
    cudaGetSymbolAddress((void**)&wqkvh_p, g_wqkvh);
    cudaGetSymbolAddress((void**)&wouth_p, g_wouth);

    static cudaStream_t s2 = nullptr;
    static cudaEvent_t evA, evB, evC, evD;
    if (!s2) {
        cudaStreamCreateWithFlags(&s2, cudaStreamNonBlocking);
        cudaEventCreateWithFlags(&evA, cudaEventDisableTiming);
        cudaEventCreateWithFlags(&evB, cudaEventDisableTiming);
        cudaEventCreateWithFlags(&evC, cudaEventDisableTiming);
        cudaEventCreateWithFlags(&evD, cudaEventDisableTiming);
        cudaFuncSetAttribute(attn_pass1,
                             cudaFuncAttributeMaxDynamicSharedMemorySize,
                             ATT_SMEM_BYTES);
        cudaFuncSetAttribute(attn_pass2,
                             cudaFuncAttributeMaxDynamicSharedMemorySize,
                             P2_SMEM_BYTES);
        cudaFuncSetAttribute(gemm_f16<EpiQKV>,
                             cudaFuncAttributeMaxDynamicSharedMemorySize,
                             GE_SMEM_BYTES);
        cudaFuncSetAttribute(gemm_f16<EpiOut>,
                             cudaFuncAttributeMaxDynamicSharedMemorySize,
                             GE_SMEM_BYTES);
    }

    // ---- fork: chaos chain on s2, LN-pre/weights on stream 0 ----
    cudaEventRecord(evA, 0);
    cudaStreamWaitEvent(s2, evA, 0);
    chaos1_kernel<<<1, 256, 0, s2>>>(cf, eW1, eb1, eg1, ebb1, Wga, bga, Wgv, bgv, Wt, bt);
    chaos2_kernel<<<64, 256, 0, s2>>>(eW2, eb2);
    chaos3_kernel<<<1, 256, 0, s2>>>(eg2, ebb2, qrot, fsc);
    cudaEventRecord(evB, s2);

    ln_pre_kernel<<<BS, 256>>>(x, lnpg, lnpb);
    round_weights<<<(3*DD*DD + DD*DD)/(256*4), 256>>>(Wqkv, Wout);
    cudaStreamWaitEvent(0, evB, 0);

    // QKV GEMM
    gemm_f16<EpiQKV><<<dim3(3*DD/128, BS/128), 256, GE_SMEM_BYTES>>>(
        xnh_p, wqkvh_p, EpiQKV{bqkv});

    // attention pass 1
    attn_pass1<<<dim3(SS/128, BH), 256, ATT_SMEM_BYTES>>>(qh_p, kh_p, vth_p);

    // ---- fork: pass2 (w write) on s2, out-proj + final on stream 0 ----
    cudaEventRecord(evC, 0);
    cudaStreamWaitEvent(s2, evC, 0);
    attn_pass2<<<dim3(SS/128, BH), 256, P2_SMEM_BYTES, s2>>>(qh_p, kh_p, wbuf);
    cudaEventRecord(evD, s2);

    gemm_f16<EpiOut><<<dim3(DD/128, BS/128), 256, GE_SMEM_BYTES>>>(
        atth_p, wouth_p, EpiOut{bout});
    final_kernel<<<BS, 256>>>(lnqg, lnqb, out);
    cudaStreamWaitEvent(0, evD, 0);
}

// round 7
// speedup vs baseline: 7.3711x; 1.0355x over previous
#include <cuda_runtime.h>
#include <cuda_fp16.h>
#include <math.h>
#include <stdint.h>

#define BB 2
#define SS 2048
#define DD 1024
#define HH 16
#define HD 64
#define CC 16
#define BS (BB*SS)
#define BH (BB*HH)

// ---------------- device scratch ----------------
__device__ __align__(256) float  g_xn[BS*DD];
__device__ __align__(256) __half g_xnh[BS*DD];
__device__ __align__(256) __half g_qh[BH*SS*HD];
__device__ __align__(256) __half g_kh[BH*SS*HD];
__device__ __align__(256) __half g_vh[BH*SS*HD];        // V row-major [bh][s][hd]
__device__ __align__(256) __half g_atth[BS*DD];
__device__ __align__(256) float  g_proj[BS*DD];
__device__ __align__(256) __half g_wqkvh[3*DD*DD];
__device__ __align__(256) __half g_wouth[DD*DD];
__device__ __align__(256) float  g_l[BH*SS];
__device__ __align__(256) float  g_w[(size_t)BH*SS*SS];

__device__ float c_h1[DD];
__device__ float c_cepre[DD];
__device__ float c_gate_a[HH];
__device__ float c_gate_v[HH];
__device__ float c_misc[2];
__device__ float c_alpha[HH];
__device__ float c_beta[HH];
__device__ float c_vadd[DD];

// ---------------- helpers ----------------
__device__ __forceinline__ uint32_t pack_h2(float a, float b) {
    __half2 h = __floats2half2_rn(a, b);
    return *reinterpret_cast<uint32_t*>(&h);
}

__device__ __forceinline__ float fast_exp2(float x) {
    float z = x + 12582912.0f;
    int   i = __float_as_int(z);
    float f = x - (z - 12582912.0f);
    float p = 9.618129e-3f;
    p = fmaf(p, f, 5.5504109e-2f);
    p = fmaf(p, f, 2.4022651e-1f);
    p = fmaf(p, f, 6.9314718e-1f);
    p = fmaf(p, f, 1.0f);
    return __int_as_float(__float_as_int(p) + (i << 23));
}

__device__ __forceinline__ void mma_f16(float c[4], const uint32_t a[4],
                                        uint32_t b0, uint32_t b1) {
    asm volatile(
        "mma.sync.aligned.m16n8k16.row.col.f32.f16.f16.f32 "
        "{%0,%1,%2,%3}, {%4,%5,%6,%7}, {%8,%9}, {%0,%1,%2,%3};"
        : "+f"(c[0]), "+f"(c[1]), "+f"(c[2]), "+f"(c[3])
        : "r"(a[0]), "r"(a[1]), "r"(a[2]), "r"(a[3]), "r"(b0), "r"(b1));
}

__device__ __forceinline__ uint32_t lds_addr(const void* p) {
    return (uint32_t)__cvta_generic_to_shared(p);
}
__device__ __forceinline__ void ldsm4(uint32_t r[4], uint32_t a) {
    asm volatile("ldmatrix.sync.aligned.m8n8.x4.shared.b16 {%0,%1,%2,%3}, [%4];"
                 : "=r"(r[0]), "=r"(r[1]), "=r"(r[2]), "=r"(r[3]) : "r"(a));
}
__device__ __forceinline__ void ldsm4t(uint32_t r[4], uint32_t a) {
    asm volatile("ldmatrix.sync.aligned.m8n8.x4.trans.shared.b16 {%0,%1,%2,%3}, [%4];"
                 : "=r"(r[0]), "=r"(r[1]), "=r"(r[2]), "=r"(r[3]) : "r"(a));
}

__device__ __forceinline__ void cp16h(__half* dst, const __half* src) {
    unsigned d = (unsigned)__cvta_generic_to_shared(dst);
    asm volatile("cp.async.cg.shared.global [%0], [%1], 16;" :: "r"(d), "l"(src));
}
__device__ __forceinline__ void cp_commit() { asm volatile("cp.async.commit_group;"); }
__device__ __forceinline__ void cp_wait1() { asm volatile("cp.async.wait_group 1;"); }
__device__ __forceinline__ void cp_wait0() { asm volatile("cp.async.wait_group 0;"); }

// ---------------- chaos encoder ----------------
__global__ void chaos1_kernel(const float* __restrict__ cf,
                              const float* __restrict__ W1, const float* __restrict__ b1,
                              const float* __restrict__ g1, const float* __restrict__ bb1,
                              const float* __restrict__ Wga, const float* __restrict__ bga,
                              const float* __restrict__ Wgv, const float* __restrict__ bgv,
                              const float* __restrict__ Wt,  const float* __restrict__ bt) {
    __shared__ float cfs[CC];
    __shared__ float red[256], red2[256];
    int t = threadIdx.x;
    if (t < CC) cfs[t] = cf[t];
    __syncthreads();

    if (t < HH) {
        float sa = bga[t], sv = bgv[t];
        #pragma unroll
        for (int c = 0; c < CC; c++) { sa += cfs[c]*Wga[t*CC+c]; sv += cfs[c]*Wgv[t*CC+c]; }
        c_gate_a[t] = 1.f/(1.f+expf(-sa));
        c_gate_v[t] = 1.f/(1.f+expf(-sv));
    } else if (t == 16) {
        float s = bt[0];
        #pragma unroll
        for (int c = 0; c < CC; c++) s += cfs[c]*Wt[c];
        float sp = (s > 20.f) ? s : log1pf(expf(s));
        c_misc[0] = sp + 1.0f;
    } else if (t == 17) {
        float s = 0.f;
        #pragma unroll
        for (int c = 0; c < CC; c++) s += cfs[c];
        s *= (1.0f/CC);
        c_misc[1] = (1.f/(1.f+expf(-s)))*0.5f + 0.5f;
    }

    float vals[4];
    float s1 = 0.f, s2 = 0.f;
    #pragma unroll
    for (int l = 0; l < 4; l++) {
        int i = t*4 + l;
        float a = b1[i];
        #pragma unroll
        for (int c = 0; c < CC; c++) a += cfs[c]*W1[i*CC+c];
        vals[l] = a; s1 += a; s2 += a*a;
    }
    red[t] = s1; red2[t] = s2; __syncthreads();
    for (int o = 128; o > 0; o >>= 1) {
        if (t < o) { red[t] += red[t+o]; red2[t] += red2[t+o]; }
        __syncthreads();
    }
    float m = red[0]*(1.0f/DD);
    float var = red2[0]*(1.0f/DD) - m*m;
    float inv = rsqrtf(var + 1e-5f);
    #pragma unroll
    for (int l = 0; l < 4; l++) {
        int i = t*4 + l;
        float h = (vals[l]-m)*inv*g1[i] + bb1[i];
        c_h1[i] = fmaxf(h, 0.f);
    }
}

__global__ void chaos2_kernel(const float* __restrict__ W2, const float* __restrict__ b2) {
    __shared__ float h1s[DD];
    __shared__ float red[256];
    int t = threadIdx.x;
    #pragma unroll
    for (int l = 0; l < 4; l++) h1s[t + l*256] = c_h1[t + l*256];
    __syncthreads();
    int r = t >> 4, c = t & 15;
    int i = blockIdx.x*16 + r;
    float s = 0.f;
    for (int j = c; j < DD; j += 16) s += h1s[j]*W2[(size_t)i*DD + j];
    red[t] = s; __syncthreads();
    for (int o = 8; o > 0; o >>= 1) {
        if (c < o) red[t] += red[t+o];
        __syncthreads();
    }
    if (c == 0) c_cepre[i] = red[r*16] + b2[i];
}

__global__ void chaos3_kernel(const float* __restrict__ g2, const float* __restrict__ bb2,
                              const float* __restrict__ qrot, const float* __restrict__ fscales) {
    __shared__ float ce[DD];
    __shared__ float scs[DD];
    __shared__ float red[256], red2[256];
    int t = threadIdx.x;
    float vals[4]; float s1 = 0.f, s2 = 0.f;
    #pragma unroll
    for (int l = 0; l < 4; l++) {
        int i = t + l*256;
        vals[l] = c_cepre[i]; s1 += vals[l]; s2 += vals[l]*vals[l];
    }
    red[t] = s1; red2[t] = s2; __syncthreads();
    for (int o = 128; o > 0; o >>= 1) {
        if (t < o) { red[t] += red[t+o]; red2[t] += red2[t+o]; }
        __syncthreads();
    }
    float m = red[0]*(1.0f/DD);
    float var = red2[0]*(1.0f/DD) - m*m;
    float inv = rsqrtf(var + 1e-5f);
    #pragma unroll
    for (int l = 0; l < 4; l++) {
        int i = t + l*256;
        ce[i] = (vals[l]-m)*inv*g2[i] + bb2[i];
    }
    __syncthreads();
    float sfs = 1.f/(1.f+expf(-fscales[0]));
    #pragma unroll
    for (int l = 0; l < 4; l++) {
        int i = t + l*256;
        int h = i >> 6, d = i & 63;
        float s = 0.f;
        #pragma unroll 8
        for (int e = 0; e < HD; e++) s += ce[h*HD+e]*qrot[e*HD+d];
        s *= sfs;
        scs[i] = s;
        c_vadd[i] = s * c_gate_v[h];
    }
    __syncthreads();
    if (t < HH) {
        float bsum = 0.f;
        for (int d = 0; d < HD; d++) bsum += scs[t*HD + d];
        float temp = c_misc[0];
        c_alpha[t] = c_gate_a[t]/(8.f*temp);
        c_beta[t]  = bsum/temp;
    }
}

// ---------------- LN-pre ----------------
__global__ void ln_pre_kernel(const float* __restrict__ x,
                              const float* __restrict__ g, const float* __restrict__ b) {
    __shared__ float red[256], red2[256];
    size_t row = blockIdx.x;
    const float4* xr = (const float4*)(x + row*DD);
    int t = threadIdx.x;
    float4 v = xr[t];
    float s1 = v.x + v.y + v.z + v.w;
    float s2 = v.x*v.x + v.y*v.y + v.z*v.z + v.w*v.w;
    red[t] = s1; red2[t] = s2; __syncthreads();
    for (int off = 128; off > 0; off >>= 1) {
        if (t < off) { red[t] += red[t+off]; red2[t] += red2[t+off]; }
        __syncthreads();
    }
    float m = red[0]*(1.0f/DD);
    float var = red2[0]*(1.0f/DD) - m*m;
    float inv = rsqrtf(var + 1e-5f);
    int i = t*4;
    float4 gg = *(const float4*)(g + i);
    float4 bb = *(const float4*)(b + i);
    float4 o;
    o.x = (v.x-m)*inv*gg.x + bb.x;
    o.y = (v.y-m)*inv*gg.y + bb.y;
    o.z = (v.z-m)*inv*gg.z + bb.z;
    o.w = (v.w-m)*inv*gg.w + bb.w;
    *(float4*)(g_xn + row*DD + i) = o;
    uint2 h;
    h.x = pack_h2(o.x, o.y);
    h.y = pack_h2(o.z, o.w);
    *(uint2*)(g_xnh + row*DD + i) = h;
}

// ---------------- convert weights to half ----------------
__global__ void round_weights(const float* __restrict__ Wqkv,
                              const float* __restrict__ Wout) {
    size_t i = (size_t)blockIdx.x*256 + threadIdx.x;
    const size_t nqkv = (size_t)3*DD*DD/4;
    float4 v;
    __half* dst;
    if (i < nqkv) {
        v = ((const float4*)Wqkv)[i];
        dst = g_wqkvh + i*4;
    } else {
        v = ((const float4*)Wout)[i - nqkv];
        dst = g_wouth + (i - nqkv)*4;
    }
    uint2 h;
    h.x = pack_h2(v.x, v.y);
    h.y = pack_h2(v.z, v.w);
    *(uint2*)dst = h;
}

// ============================================================================
// fp16 tensor-core GEMM (NT) with ldmatrix fragment loads.
// ============================================================================
#define GE_BK 64
#define GE_STR 72
#define GE_TILE_H (128*GE_STR)
#define GE_SMEM_BYTES (4*GE_TILE_H*2)

struct EpiQKV {
    const float* bias;
    __device__ __forceinline__ void write2(int m, int n, float v0, float v1) const {
        v0 += bias[n]; v1 += bias[n+1];
        int b = m >> 11, s = m & 2047;
        int which = n >> 10, rest = n & 1023;
        int h = rest >> 6, dd = rest & 63;
        int bh = b*HH + h;
        size_t dst = ((size_t)bh*SS + s)*HD + dd;
        if (which == 0) {
            *(uint32_t*)&g_qh[dst] = pack_h2(v0, v1);
        } else if (which == 1) {
            *(uint32_t*)&g_kh[dst] = pack_h2(v0, v1);
        } else {
            v0 += c_vadd[rest]; v1 += c_vadd[rest+1];
            *(uint32_t*)&g_vh[dst] = pack_h2(v0, v1);
        }
    }
};

struct EpiOut {
    const float* bias;
    __device__ __forceinline__ void write2(int m, int n, float v0, float v1) const {
        float2 o = make_float2(v0 + bias[n], v1 + bias[n+1]);
        *(float2*)&g_proj[(size_t)m*DD + n] = o;
    }
};

__device__ __forceinline__ void ge_load(__half* dstA, __half* dstB,
                                        const __half* A, const __half* B,
                                        int m0, int n0, int k0, int t) {
    #pragma unroll
    for (int i = 0; i < 4; i++) {
        int f = t + i*256;
        int row = f >> 3, c = f & 7;
        cp16h(dstA + row*GE_STR + c*8, A + (size_t)(m0+row)*DD + k0 + c*8);
    }
    #pragma unroll
    for (int i = 0; i < 4; i++) {
        int f = t + i*256;
        int row = f >> 3, c = f & 7;
        cp16h(dstB + row*GE_STR + c*8, B + (size_t)(n0+row)*DD + k0 + c*8);
    }
}

template<typename Epi>
__global__ void __launch_bounds__(256) gemm_f16(
    const __half* __restrict__ A, const __half* __restrict__ B, Epi epi)
{
    extern __shared__ __half gsm[];
    __half* As[2] = { gsm,                gsm + 2*GE_TILE_H };
    __half* Bs[2] = { gsm + GE_TILE_H,    gsm + 3*GE_TILE_H };

    int t = threadIdx.x, lane = t & 31, warp = t >> 5;
    int q = lane >> 2, r = lane & 3;
    int wm = (warp >> 1) * 32;
    int wn = (warp & 1) * 64;
    int m0 = blockIdx.y * 128, n0 = blockIdx.x * 128;

    int a_off = (wm + (lane & 15))*GE_STR + (lane >> 4)*8;
    int b_off = (wn + (lane & 7) + ((lane & 16) >> 1))*GE_STR + (lane & 8);

    float acc[2][8][4] = {};

    ge_load(As[0], Bs[0], A, B, m0, n0, 0, t);
    cp_commit();

    for (int kt = 0; kt < DD/GE_BK; kt++) {
        int cur = kt & 1;
        if (kt + 1 < DD/GE_BK) {
            ge_load(As[cur^1], Bs[cur^1], A, B, m0, n0, (kt+1)*GE_BK, t);
            cp_commit();
            cp_wait1();
        } else {
            cp_wait0();
        }
        __syncthreads();

        uint32_t asb = lds_addr(As[cur]);
        uint32_t bsb = lds_addr(Bs[cur]);
        #pragma unroll
        for (int ks = 0; ks < 4; ks++) {
            uint32_t af[2][4];
            ldsm4(af[0], asb + 2*(a_off + ks*16));
            ldsm4(af[1], asb + 2*(a_off + 16*GE_STR + ks*16));
            #pragma unroll
            for (int p = 0; p < 4; p++) {
                uint32_t bb[4];
                ldsm4(bb, bsb + 2*(b_off + p*16*GE_STR + ks*16));
                mma_f16(acc[0][2*p],   af[0], bb[0], bb[1]);
                mma_f16(acc[0][2*p+1], af[0], bb[2], bb[3]);
                mma_f16(acc[1][2*p],   af[1], bb[0], bb[1]);
                mma_f16(acc[1][2*p+1], af[1], bb[2], bb[3]);
            }
        }
        __syncthreads();
    }

    #pragma unroll
    for (int mi = 0; mi < 2; mi++)
        #pragma unroll
        for (int nj = 0; nj < 8; nj++) {
            int m = m0 + wm + mi*16 + q;
            int n = n0 + wn + nj*8 + 2*r;
            epi.write2(m,     n, acc[mi][nj][0], acc[mi][nj][1]);
            epi.write2(m + 8, n, acc[mi][nj][2], acc[mi][nj][3]);
        }
}

// ============================================================================
// Attention pass 1 (bh-half): S=QK^T -> exp2 -> rowsum + O += P@V.
// V row-major; PV B-fragments via ldmatrix.trans.
// ============================================================================
#define QS_STR 72
#define Q_HALVES (128*QS_STR)
#define ATT_SMEM_BYTES (5*Q_HALVES*2)   // Q,K0,K1,V0,V1 = 92160
#define P2_SMEM_BYTES (3*Q_HALVES*2)    // Q,K0,K1 = 55296

__device__ __forceinline__ void att_load_k(__half* dst, const __half* src, int t) {
    #pragma unroll
    for (int i = 0; i < 4; i++) {
        int f = t + i*256;
        int row = f >> 3, c = f & 7;
        cp16h(dst + row*QS_STR + c*8, src + (size_t)row*HD + c*8);
    }
}

__global__ void __launch_bounds__(256, 1) attn_pass1(
    const __half* __restrict__ qg, const __half* __restrict__ kg,
    const __half* __restrict__ vg, int bh0)
{
    extern __shared__ __half asm_[];
    __half* qs  = asm_;
    __half* ks0 = asm_ + Q_HALVES;
    __half* ks1 = asm_ + 2*Q_HALVES;
    __half* vs0 = asm_ + 3*Q_HALVES;
    __half* vs1 = asm_ + 4*Q_HALVES;
    __shared__ float l_part[2][128];

    int t = threadIdx.x, lane = t & 31, warp = t >> 5;
    int q = lane >> 2, r = lane & 3;
    int wr = warp >> 1, wc = warp & 1;
    int m0 = blockIdx.x*128, bh = bh0 + blockIdx.y;
    int h = bh & 15, b = bh >> 4;
    const __half* Q = qg + ((size_t)bh*SS + m0)*HD;
    const __half* K = kg + (size_t)bh*SS*HD;
    const __half* V = vg + (size_t)bh*SS*HD;
    const float LOG2E = 1.4426950408889634f;
    float al2 = c_alpha[h]*LOG2E, be2 = c_beta[h]*LOG2E;

    #pragma unroll
    for (int i = 0; i < 4; i++) {
        int f = t + i*256;
        int row = f >> 3, c = f & 7;
        *(uint4*)&qs[row*QS_STR + c*8] = *(const uint4*)(Q + (size_t)row*HD + c*8);
    }

    att_load_k(ks0, K, t);
    att_load_k(vs0, V, t);
    cp_commit();
    __syncthreads();

    uint32_t qf[2][4][4];
    {
        uint32_t qsb = lds_addr(qs);
        int q_off = (wr*32 + (lane & 15))*QS_STR + (lane >> 4)*8;
        #pragma unroll
        for (int mi = 0; mi < 2; mi++)
            #pragma unroll
            for (int ks = 0; ks < 4; ks++)
                ldsm4(qf[mi][ks], qsb + 2*(q_off + mi*16*QS_STR + ks*16));
    }

    int k_off = (wc*64 + (lane & 7) + ((lane & 16) >> 1))*QS_STR + (lane & 8);
    int v_off = (wc*64 + (lane & 15))*QS_STR + (lane >> 4)*8;   // trans-load addressing

    float O[2][8][4] = {};
    float rs[2][2] = {};

    for (int kt = 0; kt < 16; kt++) {
        __half* kss = (kt & 1) ? ks1 : ks0;
        __half* vss = (kt & 1) ? vs1 : vs0;
        if (kt < 15) {
            att_load_k((kt & 1) ? ks0 : ks1, K + (size_t)(kt+1)*128*HD, t);
            att_load_k((kt & 1) ? vs0 : vs1, V + (size_t)(kt+1)*128*HD, t);
            cp_commit();
            cp_wait1();
        } else {
            cp_wait0();
        }
        __syncthreads();

        // ---- S = Q K^T ----
        float acc[2][8][4] = {};
        uint32_t ksb = lds_addr(kss);
        #pragma unroll
        for (int ks = 0; ks < 4; ks++) {
            #pragma unroll
            for (int p = 0; p < 4; p++) {
                uint32_t bb[4];
                ldsm4(bb, ksb + 2*(k_off + p*16*QS_STR + ks*16));
                mma_f16(acc[0][2*p],   qf[0][ks], bb[0], bb[1]);
                mma_f16(acc[0][2*p+1], qf[0][ks], bb[2], bb[3]);
                mma_f16(acc[1][2*p],   qf[1][ks], bb[0], bb[1]);
                mma_f16(acc[1][2*p+1], qf[1][ks], bb[2], bb[3]);
            }
        }
        // ---- exp + rowsum ----
        #pragma unroll
        for (int mi = 0; mi < 2; mi++)
            #pragma unroll
            for (int nj = 0; nj < 8; nj++) {
                float e0 = fast_exp2(fmaf(al2, acc[mi][nj][0], be2));
                float e1 = fast_exp2(fmaf(al2, acc[mi][nj][1], be2));
                float e2 = fast_exp2(fmaf(al2, acc[mi][nj][2], be2));
                float e3 = fast_exp2(fmaf(al2, acc[mi][nj][3], be2));
                acc[mi][nj][0] = e0; acc[mi][nj][1] = e1;
                acc[mi][nj][2] = e2; acc[mi][nj][3] = e3;
                rs[mi][0] += e0 + e1;
                rs[mi][1] += e2 + e3;
            }
        // ---- O += P @ V  (V B-frags via ldmatrix.trans) ----
        uint32_t vsb = lds_addr(vss);
        #pragma unroll
        for (int kk = 0; kk < 4; kk++) {
            uint32_t af[2][4];
            #pragma unroll
            for (int mi = 0; mi < 2; mi++) {
                af[mi][0] = pack_h2(acc[mi][2*kk][0],   acc[mi][2*kk][1]);
                af[mi][1] = pack_h2(acc[mi][2*kk][2],   acc[mi][2*kk][3]);
                af[mi][2] = pack_h2(acc[mi][2*kk+1][0], acc[mi][2*kk+1][1]);
                af[mi][3] = pack_h2(acc[mi][2*kk+1][2], acc[mi][2*kk+1][3]);
            }
            #pragma unroll
            for (int p = 0; p < 4; p++) {
                uint32_t bb[4];
                ldsm4t(bb, vsb + 2*(v_off + kk*16*QS_STR + p*16));
                mma_f16(O[0][2*p],   af[0], bb[0], bb[1]);
                mma_f16(O[0][2*p+1], af[0], bb[2], bb[3]);
                mma_f16(O[1][2*p],   af[1], bb[0], bb[1]);
                mma_f16(O[1][2*p+1], af[1], bb[2], bb[3]);
            }
        }
        __syncthreads();
    }

    // ---- rowsum reduction ----
    #pragma unroll
    for (int mi = 0; mi < 2; mi++)
        #pragma unroll
        for (int j = 0; j < 2; j++) {
            rs[mi][j] += __shfl_xor_sync(0xffffffffu, rs[mi][j], 1);
            rs[mi][j] += __shfl_xor_sync(0xffffffffu, rs[mi][j], 2);
        }
    if (r == 0) {
        #pragma unroll
        for (int mi = 0; mi < 2; mi++)
            #pragma unroll
            for (int j = 0; j < 2; j++)
                l_part[wc][wr*32 + mi*16 + j*8 + q] = rs[mi][j];
    }
    __syncthreads();
    float inv[2][2];
    #pragma unroll
    for (int mi = 0; mi < 2; mi++)
        #pragma unroll
        for (int j = 0; j < 2; j++) {
            int row = wr*32 + mi*16 + j*8 + q;
            float l = l_part[0][row] + l_part[1][row];
            inv[mi][j] = 1.0f / l;
            if (wc == 0 && r == 0)
                g_l[(size_t)bh*SS + m0 + row] = l;
        }

    // ---- O cross-warp reduction + store ----
    float* scr = (float*)vs0;
    if (wc == 1) {
        #pragma unroll
        for (int mi = 0; mi < 2; mi++)
            #pragma unroll
            for (int nj = 0; nj < 8; nj++)
                #pragma unroll
                for (int p = 0; p < 4; p++) {
                    int idx = (mi*8 + nj)*4 + p;
                    scr[(wr*64 + idx)*32 + lane] = O[mi][nj][p];
                }
    }
    __syncthreads();
    if (wc == 0) {
        #pragma unroll
        for (int mi = 0; mi < 2; mi++)
            #pragma unroll
            for (int nj = 0; nj < 8; nj++) {
                #pragma unroll
                for (int p = 0; p < 4; p++) {
                    int idx = (mi*8 + nj)*4 + p;
                    O[mi][nj][p] += scr[(wr*64 + idx)*32 + lane];
                }
                int row = m0 + wr*32 + mi*16 + q;
                int col = h*64 + nj*8 + 2*r;
                *(uint32_t*)&g_atth[((size_t)(b*SS + row))*DD + col] =
                    pack_h2(O[mi][nj][0]*inv[mi][0], O[mi][nj][1]*inv[mi][0]);
                *(uint32_t*)&g_atth[((size_t)(b*SS + row + 8))*DD + col] =
                    pack_h2(O[mi][nj][2]*inv[mi][1], O[mi][nj][3]*inv[mi][1]);
            }
    }
}

// ============================================================================
// Attention pass 2 (bh-half): recompute S, write w.
// ============================================================================
__global__ void __launch_bounds__(256, 2) attn_pass2(
    const __half* __restrict__ qg, const __half* __restrict__ kg,
    float* __restrict__ wout, int bh0)
{
    extern __shared__ __half asm2_[];
    __half* qs  = asm2_;
    __half* ks0 = asm2_ + Q_HALVES;
    __half* ks1 = asm2_ + 2*Q_HALVES;

    int t = threadIdx.x, lane = t & 31, warp = t >> 5;
    int q = lane >> 2, r = lane & 3;
    int wr = warp >> 1, wc = warp & 1;
    int m0 = blockIdx.x*128, bh = bh0 + blockIdx.y;
    int h = bh & 15;
    const __half* Q = qg + ((size_t)bh*SS + m0)*HD;
    const __half* K = kg + (size_t)bh*SS*HD;
    const float LOG2E = 1.4426950408889634f;
    float al2 = c_alpha[h]*LOG2E, be2 = c_beta[h]*LOG2E;

    #pragma unroll
    for (int i = 0; i < 4; i++) {
        int f = t + i*256;
        int row = f >> 3, c = f & 7;
        *(uint4*)&qs[row*QS_STR + c*8] = *(const uint4*)(Q + (size_t)row*HD + c*8);
    }
    att_load_k(ks0, K, t);
    cp_commit();

    float cc[2][2];
    #pragma unroll
    for (int mi = 0; mi < 2; mi++)
        #pragma unroll
        for (int j = 0; j < 2; j++) {
            int row = wr*32 + mi*16 + j*8 + q;
            cc[mi][j] = be2 - __log2f(g_l[(size_t)bh*SS + m0 + row]);
        }
    __syncthreads();

    uint32_t qf[2][4][4];
    {
        uint32_t qsb = lds_addr(qs);
        int q_off = (wr*32 + (lane & 15))*QS_STR + (lane >> 4)*8;
        #pragma unroll
        for (int mi = 0; mi < 2; mi++)
            #pragma unroll
            for (int ks = 0; ks < 4; ks++)
                ldsm4(qf[mi][ks], qsb + 2*(q_off + mi*16*QS_STR + ks*16));
    }
    int k_off = (wc*64 + (lane & 7) + ((lane & 16) >> 1))*QS_STR + (lane & 8);

    float* wbh = wout + (size_t)bh*SS*SS;
    for (int kt = 0; kt < 16; kt++) {
        __half* kss = (kt & 1) ? ks1 : ks0;
        if (kt < 15) {
            att_load_k((kt & 1) ? ks0 : ks1, K + (size_t)(kt+1)*128*HD, t);
            cp_commit();
            cp_wait1();
        } else {
            cp_wait0();
        }
        __syncthreads();

        float acc[2][8][4] = {};
        uint32_t ksb = lds_addr(kss);
        #pragma unroll
        for (int ks = 0; ks < 4; ks++) {
            #pragma unroll
            for (int p = 0; p < 4; p++) {
                uint32_t bb[4];
                ldsm4(bb, ksb + 2*(k_off + p*16*QS_STR + ks*16));
                mma_f16(acc[0][2*p],   qf[0][ks], bb[0], bb[1]);
                mma_f16(acc[0][2*p+1], qf[0][ks], bb[2], bb[3]);
                mma_f16(acc[1][2*p],   qf[1][ks], bb[0], bb[1]);
                mma_f16(acc[1][2*p+1], qf[1][ks], bb[2], bb[3]);
            }
        }
        #pragma unroll
        for (int mi = 0; mi < 2; mi++) {
            int row = m0 + wr*32 + mi*16 + q;
            #pragma unroll
            for (int nj = 0; nj < 8; nj++) {
                int col = kt*128 + wc*64 + nj*8 + 2*r;
                float e0 = fast_exp2(fmaf(al2, acc[mi][nj][0], cc[mi][0]));
                float e1 = fast_exp2(fmaf(al2, acc[mi][nj][1], cc[mi][0]));
                float e2 = fast_exp2(fmaf(al2, acc[mi][nj][2], cc[mi][1]));
                float e3 = fast_exp2(fmaf(al2, acc[mi][nj][3], cc[mi][1]));
                __stcs((float2*)&wbh[(size_t)row*SS + col], make_float2(e0, e1));
                __stcs((float2*)&wbh[(size_t)(row+8)*SS + col], make_float2(e2, e3));
            }
        }
        __syncthreads();
    }
}

// ---------------- final: mix + LN-post ----------------
__global__ void final_kernel(const float* __restrict__ g, const float* __restrict__ b,
                             float* __restrict__ out) {
    __shared__ float red[256], red2[256];
    size_t row = blockIdx.x;
    int t = threadIdx.x;
    float gm = c_misc[1];
    float vals[4]; float s1 = 0.f, s2 = 0.f;
    #pragma unroll
    for (int l = 0; l < 4; l++) {
        size_t idx = row*DD + t + l*256;
        float vv = g_proj[idx]*gm + g_xn[idx]*(1.f - gm);
        vals[l] = vv; s1 += vv; s2 += vv*vv;
    }
    red[t] = s1; red2[t] = s2; __syncthreads();
    for (int off = 128; off > 0; off >>= 1) {
        if (t < off) { red[t] += red[t+off]; red2[t] += red2[t+off]; }
        __syncthreads();
    }
    float m = red[0]*(1.0f/DD);
    float var = red2[0]*(1.0f/DD) - m*m;
    float inv = rsqrtf(var + 1e-5f);
    #pragma unroll
    for (int l = 0; l < 4; l++) {
        int i = t + l*256;
        out[row*DD + i] = (vals[l]-m)*inv*g[i] + b[i];
    }
}

// ---------------------------------------------------------------------------
extern "C" void kernel_launch(void* const* d_in, const int* in_sizes, int n_in,
                              void* d_out, int out_size) {
    const float* x      = (const float*)d_in[0];
    const float* cf     = (const float*)d_in[1];
    const float* lnpg   = (const float*)d_in[2];
    const float* lnpb   = (const float*)d_in[3];
    const float* Wqkv   = (const float*)d_in[4];
    const float* bqkv   = (const float*)d_in[5];
    const float* eW1    = (const float*)d_in[6];
    const float* eb1    = (const float*)d_in[7];
    const float* eg1    = (const float*)d_in[8];
    const float* ebb1   = (const float*)d_in[9];
    const float* eW2    = (const float*)d_in[10];
    const float* eb2    = (const float*)d_in[11];
    const float* eg2    = (const float*)d_in[12];
    const float* ebb2   = (const float*)d_in[13];
    const float* Wga    = (const float*)d_in[14];
    const float* bga    = (const float*)d_in[15];
    const float* Wgv    = (const float*)d_in[16];
    const float* bgv    = (const float*)d_in[17];
    const float* Wt     = (const float*)d_in[18];
    const float* bt     = (const float*)d_in[19];
    const float* qrot   = (const float*)d_in[20];
    const float* fsc    = (const float*)d_in[21];
    const float* Wout   = (const float*)d_in[22];
    const float* bout   = (const float*)d_in[23];
    const float* lnqg   = (const float*)d_in[24];
    const float* lnqb   = (const float*)d_in[25];

    float* out = (float*)d_out;

    size_t need = (size_t)BS*DD + (size_t)BH*SS*SS;
    float* wbuf;
    if ((size_t)out_size >= need) {
        wbuf = out + (size_t)BS*DD;
    } else {
        float* wptr = nullptr;
        cudaGetSymbolAddress((void**)&wptr, g_w);
        wbuf = wptr;
    }

    __half *xnh_p, *qh_p, *kh_p, *vh_p, *atth_p, *wqkvh_p, *wouth_p;
    cudaGetSymbolAddress((void**)&xnh_p,   g_xnh);
    cudaGetSymbolAddress((void**)&qh_p,    g_qh);
    cudaGetSymbolAddress((void**)&kh_p,    g_kh);
    cudaGetSymbolAddress((void**)&vh_p,    g_vh);
    cudaGetSymbolAddress((void**)&atth_p,  g_atth);
    cudaGetSymbolAddress((void**)&wqkvh_p, g_wqkvh);
    cudaGetSymbolAddress((void**)&wouth_p, g_wouth);

    static cudaStream_t s2 = nullptr;
    static cudaEvent_t evA, evB, ev1, ev2, evD;
    if (!s2) {
        cudaStreamCreateWithFlags(&s2, cudaStreamNonBlocking);
        cudaEventCreateWithFlags(&evA, cudaEventDisableTiming);
        cudaEventCreateWithFlags(&evB, cudaEventDisableTiming);
        cudaEventCreateWithFlags(&ev1, cudaEventDisableTiming);
        cudaEventCreateWithFlags(&ev2, cudaEventDisableTiming);
        cudaEventCreateWithFlags(&evD, cudaEventDisableTiming);
        cudaFuncSetAttribute(attn_pass1,
                             cudaFuncAttributeMaxDynamicSharedMemorySize,
                             ATT_SMEM_BYTES);
        cudaFuncSetAttribute(attn_pass2,
                             cudaFuncAttributeMaxDynamicSharedMemorySize,
                             P2_SMEM_BYTES);
        cudaFuncSetAttribute(gemm_f16<EpiQKV>,
                             cudaFuncAttributeMaxDynamicSharedMemorySize,
                             GE_SMEM_BYTES);
        cudaFuncSetAttribute(gemm_f16<EpiOut>,
                             cudaFuncAttributeMaxDynamicSharedMemorySize,
                             GE_SMEM_BYTES);
    }

    // ---- fork: chaos chain + weight rounding on s2, LN-pre on stream 0 ----
    cudaEventRecord(evA, 0);
    cudaStreamWaitEvent(s2, evA, 0);
    chaos1_kernel<<<1, 256, 0, s2>>>(cf, eW1, eb1, eg1, ebb1, Wga, bga, Wgv, bgv, Wt, bt);
    chaos2_kernel<<<64, 256, 0, s2>>>(eW2, eb2);
    chaos3_kernel<<<1, 256, 0, s2>>>(eg2, ebb2, qrot, fsc);
    round_weights<<<(3*DD*DD + DD*DD)/(256*4), 256, 0, s2>>>(Wqkv, Wout);
    cudaEventRecord(evB, s2);

    ln_pre_kernel<<<BS, 256>>>(x, lnpg, lnpb);
    cudaStreamWaitEvent(0, evB, 0);

    // QKV GEMM
    gemm_f16<EpiQKV><<<dim3(3*DD/128, BS/128), 256, GE_SMEM_BYTES>>>(
        xnh_p, wqkvh_p, EpiQKV{bqkv});

    // ---- pipelined attention: pass1 halves; pass2 overlapped on s2 ----
    attn_pass1<<<dim3(SS/128, BH/2), 256, ATT_SMEM_BYTES>>>(qh_p, kh_p, vh_p, 0);
    cudaEventRecord(ev1, 0);
    cudaStreamWaitEvent(s2, ev1, 0);
    attn_pass2<<<dim3(SS/128, BH/2), 256, P2_SMEM_BYTES, s2>>>(qh_p, kh_p, wbuf, 0);

    attn_pass1<<<dim3(SS/128, BH/2), 256, ATT_SMEM_BYTES>>>(qh_p, kh_p, vh_p, BH/2);
    cudaEventRecord(ev2, 0);
    cudaStreamWaitEvent(s2, ev2, 0);
    attn_pass2<<<dim3(SS/128, BH/2), 256, P2_SMEM_BYTES, s2>>>(qh_p, kh_p, wbuf, BH/2);
    cudaEventRecord(evD, s2);

    // out projection + final on stream 0 (overlap with pass2-B)
    gemm_f16<EpiOut><<<dim3(DD/128, BS/128), 256, GE_SMEM_BYTES>>>(
        atth_p, wouth_p, EpiOut{bout});
    final_kernel<<<BS, 256>>>(lnqg, lnqb, out);
    cudaStreamWaitEvent(0, evD, 0);
}